// round 2
// baseline (speedup 1.0000x reference)
#include <cuda_runtime.h>
#include <cuda_bf16.h>
#include <math_constants.h>

// ---------------------------------------------------------------------------
// RelativeAttention: B=8, N=1024, C=768, H=12, hd=64, MAX_DIST=32
//   qkv = x @ qkv_w                      [8192, 2304]
//   per (b,h): attn = softmax(q k^T * 0.125 + bias), ctx = attn @ v
//   out = ctx @ proj_w + proj_b          [8192, 768]
// rel_index is analytic: idx = ((i>>5)-(j>>5)+31)*63 + ((i&31)-(j&31)+31)
// ---------------------------------------------------------------------------

#define BATCH   8
#define SEQ     1024
#define DIM     768
#define HEADS   12
#define HDIM    64
#define ROWS    (BATCH * SEQ)       // 8192
#define QKVCOLS (3 * DIM)           // 2304

// scratch (device globals: allocation-free)
__device__ float g_qkv[ROWS * QKVCOLS];   // ~75.5 MB
__device__ float g_ctx[ROWS * DIM];       // ~25.2 MB

// ---------------------------------------------------------------------------
// SGEMM: C[M,N] = A[M,K] @ B[K,N] (+ bias[N]); 128x128 block, 16 K-slice,
// 256 threads, 8x8 per-thread tile split into 4x 4x4 strips.
// Requires M%128==0, N%128==0, K%16==0 (true for all calls here).
// ---------------------------------------------------------------------------
__global__ __launch_bounds__(256, 2)
void sgemm128(const float* __restrict__ A, const float* __restrict__ B,
              const float* __restrict__ bias, float* __restrict__ C,
              int M, int N, int K)
{
    __shared__ float As[16][132];   // [BK][BM+4]
    __shared__ float Bs[16][132];   // [BK][BN+4]

    const int tid = threadIdx.x;
    const int bm  = blockIdx.y * 128;
    const int bn  = blockIdx.x * 128;

    const int tr0 = (tid >> 4) * 4;   // 0..60
    const int tc0 = (tid & 15) * 4;   // 0..60

    const int a_row = tid >> 2;         // 0..63
    const int a_col = (tid & 3) * 4;    // 0,4,8,12
    const int b_row = tid >> 5;         // 0..7
    const int b_col = (tid & 31) * 4;   // 0..124

    float acc[8][8];
#pragma unroll
    for (int i = 0; i < 8; i++)
#pragma unroll
        for (int j = 0; j < 8; j++) acc[i][j] = 0.f;

    const float* Ab = A + (size_t)bm * K;
    const float* Bb = B + bn;

    for (int k0 = 0; k0 < K; k0 += 16) {
        float4 a0 = *(const float4*)(Ab + (size_t)a_row        * K + k0 + a_col);
        float4 a1 = *(const float4*)(Ab + (size_t)(a_row + 64) * K + k0 + a_col);
        float4 b0 = *(const float4*)(Bb + (size_t)(k0 + b_row)     * N + b_col);
        float4 b1 = *(const float4*)(Bb + (size_t)(k0 + b_row + 8) * N + b_col);

        As[a_col + 0][a_row] = a0.x;
        As[a_col + 1][a_row] = a0.y;
        As[a_col + 2][a_row] = a0.z;
        As[a_col + 3][a_row] = a0.w;
        As[a_col + 0][a_row + 64] = a1.x;
        As[a_col + 1][a_row + 64] = a1.y;
        As[a_col + 2][a_row + 64] = a1.z;
        As[a_col + 3][a_row + 64] = a1.w;
        *(float4*)&Bs[b_row][b_col]     = b0;
        *(float4*)&Bs[b_row + 8][b_col] = b1;
        __syncthreads();

#pragma unroll
        for (int kk = 0; kk < 16; kk++) {
            float ra[8], rb[8];
#pragma unroll
            for (int i = 0; i < 4; i++) {
                ra[i]     = As[kk][tr0 + i];
                ra[i + 4] = As[kk][64 + tr0 + i];
                rb[i]     = Bs[kk][tc0 + i];
                rb[i + 4] = Bs[kk][64 + tc0 + i];
            }
#pragma unroll
            for (int i = 0; i < 8; i++)
#pragma unroll
                for (int j = 0; j < 8; j++)
                    acc[i][j] = fmaf(ra[i], rb[j], acc[i][j]);
        }
        __syncthreads();
    }

    // epilogue
#pragma unroll
    for (int ih = 0; ih < 2; ih++) {
#pragma unroll
        for (int i = 0; i < 4; i++) {
            int r = bm + ih * 64 + tr0 + i;
            float* crow = C + (size_t)r * N + bn;
#pragma unroll
            for (int jh = 0; jh < 2; jh++) {
                float4 v;
                v.x = acc[ih * 4 + i][jh * 4 + 0];
                v.y = acc[ih * 4 + i][jh * 4 + 1];
                v.z = acc[ih * 4 + i][jh * 4 + 2];
                v.w = acc[ih * 4 + i][jh * 4 + 3];
                if (bias) {
                    int c = bn + jh * 64 + tc0;
                    v.x += __ldg(&bias[c + 0]);
                    v.y += __ldg(&bias[c + 1]);
                    v.z += __ldg(&bias[c + 2]);
                    v.w += __ldg(&bias[c + 3]);
                }
                *(float4*)(crow + jh * 64 + tc0) = v;
            }
        }
    }
}

// ---------------------------------------------------------------------------
// Flash attention with relative bias.
// grid = (SEQ/64, B*H); block = 256 threads.
// Thread layout: row = tid>>2 (64 query rows), l4 = tid&3.
//   S: thread covers keys j = jj*4 + l4 (interleaved; 16 keys)
//   O: thread covers d-cols d = l4*16 + dd (blocked; 16 cols)
// ---------------------------------------------------------------------------
#define FA_SMEM (4 * 64 * 68 * 4)   // Qs,Ks,Vs,Ps each 64x68 floats = 69632 B

__global__ __launch_bounds__(256)
void flash_attn(const float* __restrict__ qkv,
                const float* __restrict__ bias_table,
                float* __restrict__ ctx)
{
    extern __shared__ float sm[];
    float* Qs = sm;                 // 64 x 68
    float* Ks = Qs + 64 * 68;
    float* Vs = Ks + 64 * 68;
    float* Ps = Vs + 64 * 68;

    const int bh = blockIdx.y;
    const int b  = bh / HEADS;
    const int h  = bh % HEADS;
    const int r0 = blockIdx.x * 64;

    const int tid = threadIdx.x;
    const int row = tid >> 2;       // 0..63
    const int l4  = tid & 3;        // 0..3

    // ---- load Q tile (scaled by 1/sqrt(hd) = 0.125) ----
    const int lr = tid >> 2;
    {
        const float* qbase = qkv + ((size_t)(b * SEQ + r0) * QKVCOLS) + h * HDIM;
#pragma unroll
        for (int k = 0; k < 4; k++) {
            int c = ((tid & 3) + 4 * k) * 4;
            float4 v = *(const float4*)(qbase + (size_t)lr * QKVCOLS + c);
            v.x *= 0.125f; v.y *= 0.125f; v.z *= 0.125f; v.w *= 0.125f;
            *(float4*)&Qs[lr * 68 + c] = v;
        }
    }

    float m_i = -CUDART_INF_F;
    float l_i = 0.f;
    float4 o[4];
#pragma unroll
    for (int dd = 0; dd < 4; dd++) o[dd] = make_float4(0.f, 0.f, 0.f, 0.f);

    const int gi    = r0 + row;
    const int gi_hi = gi >> 5;
    const int gi_lo = gi & 31;

    for (int t = 0; t < SEQ / 64; t++) {
        __syncthreads();
        // ---- load K and V tiles ----
        {
            const float* kbase = qkv + ((size_t)(b * SEQ + t * 64) * QKVCOLS) + DIM + h * HDIM;
            const float* vbase = kbase + DIM;
#pragma unroll
            for (int k = 0; k < 4; k++) {
                int c = ((tid & 3) + 4 * k) * 4;
                *(float4*)&Ks[lr * 68 + c] = *(const float4*)(kbase + (size_t)lr * QKVCOLS + c);
                *(float4*)&Vs[lr * 68 + c] = *(const float4*)(vbase + (size_t)lr * QKVCOLS + c);
            }
        }
        __syncthreads();

        // ---- S = Q K^T (16 scores per thread, interleaved keys) ----
        float s[16];
#pragma unroll
        for (int jj = 0; jj < 16; jj++) s[jj] = 0.f;
#pragma unroll
        for (int d4 = 0; d4 < 16; d4++) {
            float4 q = *(const float4*)&Qs[row * 68 + d4 * 4];
#pragma unroll
            for (int jj = 0; jj < 16; jj++) {
                int j = (jj << 2) | l4;
                float4 kv = *(const float4*)&Ks[j * 68 + d4 * 4];
                s[jj] = fmaf(q.x, kv.x, s[jj]);
                s[jj] = fmaf(q.y, kv.y, s[jj]);
                s[jj] = fmaf(q.z, kv.z, s[jj]);
                s[jj] = fmaf(q.w, kv.w, s[jj]);
            }
        }

        // ---- add relative bias (analytic rel_index), row-max ----
        float mt = -CUDART_INF_F;
#pragma unroll
        for (int jj = 0; jj < 16; jj++) {
            int jg  = t * 64 + ((jj << 2) | l4);
            int ri0 = gi_hi - (jg >> 5) + 31;
            int ri1 = gi_lo - (jg & 31) + 31;
            s[jj] += __ldg(&bias_table[(ri0 * 63 + ri1) * HEADS + h]);
            mt = fmaxf(mt, s[jj]);
        }
        mt = fmaxf(mt, __shfl_xor_sync(0xffffffffu, mt, 1));
        mt = fmaxf(mt, __shfl_xor_sync(0xffffffffu, mt, 2));

        float m_new = fmaxf(m_i, mt);
        float alpha = __expf(m_i - m_new);

        float lsum = 0.f;
#pragma unroll
        for (int jj = 0; jj < 16; jj++) {
            float p = __expf(s[jj] - m_new);
            lsum += p;
            Ps[row * 68 + ((jj << 2) | l4)] = p;
        }
        lsum += __shfl_xor_sync(0xffffffffu, lsum, 1);
        lsum += __shfl_xor_sync(0xffffffffu, lsum, 2);

        l_i = l_i * alpha + lsum;
        m_i = m_new;
#pragma unroll
        for (int dd = 0; dd < 4; dd++) {
            o[dd].x *= alpha; o[dd].y *= alpha; o[dd].z *= alpha; o[dd].w *= alpha;
        }
        __syncwarp();   // Ps[row][*] written by 4 lanes of this warp; order before read

        // ---- O += P V ----
#pragma unroll 8
        for (int j = 0; j < 64; j++) {
            float p = Ps[row * 68 + j];
#pragma unroll
            for (int dd = 0; dd < 4; dd++) {
                float4 v = *(const float4*)&Vs[j * 68 + (l4 * 4 + dd) * 4];
                o[dd].x = fmaf(p, v.x, o[dd].x);
                o[dd].y = fmaf(p, v.y, o[dd].y);
                o[dd].z = fmaf(p, v.z, o[dd].z);
                o[dd].w = fmaf(p, v.w, o[dd].w);
            }
        }
    }

    // ---- normalize, write ctx[b, gi, h*64 + d] ----
    float inv = 1.f / l_i;
    float* obase = ctx + (size_t)(b * SEQ + gi) * DIM + h * HDIM + l4 * 16;
#pragma unroll
    for (int dd = 0; dd < 4; dd++) {
        float4 v = o[dd];
        v.x *= inv; v.y *= inv; v.z *= inv; v.w *= inv;
        *(float4*)(obase + dd * 4) = v;
    }
}

// ---------------------------------------------------------------------------
extern "C" void kernel_launch(void* const* d_in, const int* in_sizes, int n_in,
                              void* d_out, int out_size)
{
    const float* x          = (const float*)d_in[0];
    const float* qkv_w      = (const float*)d_in[1];
    const float* proj_w     = (const float*)d_in[2];
    const float* proj_b     = (const float*)d_in[3];
    const float* bias_table = (const float*)d_in[4];
    // d_in[5] = rel_index (int32) — computed analytically, unused
    float* out = (float*)d_out;

    float *qkv_s, *ctx_s;
    cudaGetSymbolAddress((void**)&qkv_s, g_qkv);
    cudaGetSymbolAddress((void**)&ctx_s, g_ctx);

    // 1) qkv = x @ qkv_w
    {
        dim3 grid(QKVCOLS / 128, ROWS / 128);
        sgemm128<<<grid, 256>>>(x, qkv_w, nullptr, qkv_s, ROWS, QKVCOLS, DIM);
    }

    // 2) flash attention
    {
        cudaFuncSetAttribute(flash_attn, cudaFuncAttributeMaxDynamicSharedMemorySize, FA_SMEM);
        dim3 grid(SEQ / 64, BATCH * HEADS);
        flash_attn<<<grid, 256, FA_SMEM>>>(qkv_s, bias_table, ctx_s);
    }

    // 3) out = ctx @ proj_w + proj_b
    {
        dim3 grid(DIM / 128, ROWS / 128);
        sgemm128<<<grid, 256>>>(ctx_s, proj_w, proj_b, out, ROWS, DIM, DIM);
    }
}

// round 5
// speedup vs baseline: 2.4359x; 2.4359x over previous
#include <cuda_runtime.h>
#include <cuda_bf16.h>
#include <math_constants.h>
#include <cstdint>

// ---------------------------------------------------------------------------
// RelativeAttention: B=8, N=1024, C=768, H=12, hd=64, MAX_DIST=32
//   qkv = x @ qkv_w                      [8192, 2304]   (fp32 SIMT GEMM)
//   per (b,h): attn = softmax(q k^T * 0.125 + bias), ctx = attn @ v
//              (tf32 mma.sync flash attention)
//   out = ctx @ proj_w + proj_b          [8192, 768]    (fp32 SIMT GEMM)
// rel_index is analytic: idx = ((i>>5)-(j>>5)+31)*63 + ((i&31)-(j&31)+31)
// ---------------------------------------------------------------------------

#define BATCH   8
#define SEQ     1024
#define DIM     768
#define HEADS   12
#define HDIM    64
#define ROWS    (BATCH * SEQ)       // 8192
#define QKVCOLS (3 * DIM)           // 2304

// scratch (device globals: allocation-free)
__device__ float g_qkv[ROWS * QKVCOLS];   // ~75.5 MB
__device__ float g_ctx[ROWS * DIM];       // ~25.2 MB

// ---------------------------------------------------------------------------
// SGEMM: C[M,N] = A[M,K] @ B[K,N] (+ bias[N]); 128x128 block, 16 K-slice.
// ---------------------------------------------------------------------------
__global__ __launch_bounds__(256, 2)
void sgemm128(const float* __restrict__ A, const float* __restrict__ B,
              const float* __restrict__ bias, float* __restrict__ C,
              int M, int N, int K)
{
    __shared__ float As[16][132];
    __shared__ float Bs[16][132];

    const int tid = threadIdx.x;
    const int bm  = blockIdx.y * 128;
    const int bn  = blockIdx.x * 128;

    const int tr0 = (tid >> 4) * 4;
    const int tc0 = (tid & 15) * 4;

    const int a_row = tid >> 2;
    const int a_col = (tid & 3) * 4;
    const int b_row = tid >> 5;
    const int b_col = (tid & 31) * 4;

    float acc[8][8];
#pragma unroll
    for (int i = 0; i < 8; i++)
#pragma unroll
        for (int j = 0; j < 8; j++) acc[i][j] = 0.f;

    const float* Ab = A + (size_t)bm * K;
    const float* Bb = B + bn;

    for (int k0 = 0; k0 < K; k0 += 16) {
        float4 a0 = *(const float4*)(Ab + (size_t)a_row        * K + k0 + a_col);
        float4 a1 = *(const float4*)(Ab + (size_t)(a_row + 64) * K + k0 + a_col);
        float4 b0 = *(const float4*)(Bb + (size_t)(k0 + b_row)     * N + b_col);
        float4 b1 = *(const float4*)(Bb + (size_t)(k0 + b_row + 8) * N + b_col);

        As[a_col + 0][a_row] = a0.x;
        As[a_col + 1][a_row] = a0.y;
        As[a_col + 2][a_row] = a0.z;
        As[a_col + 3][a_row] = a0.w;
        As[a_col + 0][a_row + 64] = a1.x;
        As[a_col + 1][a_row + 64] = a1.y;
        As[a_col + 2][a_row + 64] = a1.z;
        As[a_col + 3][a_row + 64] = a1.w;
        *(float4*)&Bs[b_row][b_col]     = b0;
        *(float4*)&Bs[b_row + 8][b_col] = b1;
        __syncthreads();

#pragma unroll
        for (int kk = 0; kk < 16; kk++) {
            float ra[8], rb[8];
#pragma unroll
            for (int i = 0; i < 4; i++) {
                ra[i]     = As[kk][tr0 + i];
                ra[i + 4] = As[kk][64 + tr0 + i];
                rb[i]     = Bs[kk][tc0 + i];
                rb[i + 4] = Bs[kk][64 + tc0 + i];
            }
#pragma unroll
            for (int i = 0; i < 8; i++)
#pragma unroll
                for (int j = 0; j < 8; j++)
                    acc[i][j] = fmaf(ra[i], rb[j], acc[i][j]);
        }
        __syncthreads();
    }

#pragma unroll
    for (int ih = 0; ih < 2; ih++) {
#pragma unroll
        for (int i = 0; i < 4; i++) {
            int r = bm + ih * 64 + tr0 + i;
            float* crow = C + (size_t)r * N + bn;
#pragma unroll
            for (int jh = 0; jh < 2; jh++) {
                float4 v;
                v.x = acc[ih * 4 + i][jh * 4 + 0];
                v.y = acc[ih * 4 + i][jh * 4 + 1];
                v.z = acc[ih * 4 + i][jh * 4 + 2];
                v.w = acc[ih * 4 + i][jh * 4 + 3];
                if (bias) {
                    int c = bn + jh * 64 + tc0;
                    v.x += __ldg(&bias[c + 0]);
                    v.y += __ldg(&bias[c + 1]);
                    v.z += __ldg(&bias[c + 2]);
                    v.w += __ldg(&bias[c + 3]);
                }
                *(float4*)(crow + jh * 64 + tc0) = v;
            }
        }
    }
}

// ---------------------------------------------------------------------------
// tf32 helpers
// ---------------------------------------------------------------------------
__device__ __forceinline__ uint32_t f2tf32(float x) {
    uint32_t r;
    asm("cvt.rna.tf32.f32 %0, %1;" : "=r"(r) : "f"(x));
    return r;
}

__device__ __forceinline__ void mma_tf32(float c[4], const uint32_t a[4], const uint32_t b[2]) {
    asm volatile(
        "mma.sync.aligned.m16n8k8.row.col.f32.tf32.tf32.f32 "
        "{%0,%1,%2,%3}, {%4,%5,%6,%7}, {%8,%9}, {%0,%1,%2,%3};\n"
        : "+f"(c[0]), "+f"(c[1]), "+f"(c[2]), "+f"(c[3])
        : "r"(a[0]), "r"(a[1]), "r"(a[2]), "r"(a[3]), "r"(b[0]), "r"(b[1]));
}

// ---------------------------------------------------------------------------
// Flash attention with relative bias, tf32 tensor cores.
// grid = (SEQ/128, B*H); block = 256 (8 warps). Each warp: 16 query rows.
// Per key-tile (64 keys): S = Q K^T (mma), softmax in registers, P via smem,
// O += P V (mma).
// smem: Ks 64x68 fp32 | Vs 64x68 fp32 | Ps 8*(16x68) fp32  = 69632 B
// ---------------------------------------------------------------------------
#define QTILE 128
#define KTILE 64
#define LDK   68
#define FA_SMEM ((2 * 64 * LDK + 8 * 16 * LDK) * 4)

__global__ __launch_bounds__(256)
void flash_attn_tc(const float* __restrict__ qkv,
                   const float* __restrict__ bias_table,
                   float* __restrict__ ctx)
{
    extern __shared__ float sm[];
    float* Ks = sm;                    // 64 x 68 (tf32 bits)
    float* Vs = Ks + 64 * LDK;         // 64 x 68 (tf32 bits)
    float* Ps = Vs + 64 * LDK;         // 8 warps x 16 x 68

    const int bh = blockIdx.y;
    const int b  = bh / HEADS;
    const int h  = bh % HEADS;
    const int r0 = blockIdx.x * QTILE;

    const int tid  = threadIdx.x;
    const int wid  = tid >> 5;
    const int lane = tid & 31;
    const int g    = lane >> 2;     // 0..7
    const int t    = lane & 3;      // 0..3

    float* Pw = Ps + wid * 16 * LDK;

    // ---- load Q A-fragments (16 rows per warp), scaled, tf32 ----
    uint32_t qa[8][4];
    {
        const int qr0 = b * SEQ + r0 + wid * 16;
        const float* qb = qkv + (size_t)qr0 * QKVCOLS + h * HDIM;
#pragma unroll
        for (int kk = 0; kk < 8; kk++) {
            qa[kk][0] = f2tf32(0.125f * __ldg(qb + (size_t)g       * QKVCOLS + kk * 8 + t));
            qa[kk][1] = f2tf32(0.125f * __ldg(qb + (size_t)(g + 8) * QKVCOLS + kk * 8 + t));
            qa[kk][2] = f2tf32(0.125f * __ldg(qb + (size_t)g       * QKVCOLS + kk * 8 + t + 4));
            qa[kk][3] = f2tf32(0.125f * __ldg(qb + (size_t)(g + 8) * QKVCOLS + kk * 8 + t + 4));
        }
    }

    float o[8][4];
#pragma unroll
    for (int nt = 0; nt < 8; nt++)
#pragma unroll
        for (int c = 0; c < 4; c++) o[nt][c] = 0.f;

    float m0 = -CUDART_INF_F, m1 = -CUDART_INF_F;
    float l0 = 0.f, l1 = 0.f;

    // query row indices for bias
    const int i0 = r0 + wid * 16 + g;
    const int i1 = i0 + 8;
    const int i0hi = i0 >> 5, i0lo = i0 & 31;
    const int i1hi = i1 >> 5, i1lo = i1 & 31;
    const float* btab = bias_table + h;

    const int lr = tid >> 2;        // 0..63 (K/V tile loader row)
    const int lc = (tid & 3) * 4;   // base float4 col

    for (int tk = 0; tk < SEQ / KTILE; tk++) {
        __syncthreads();
        // ---- stage K,V tile into smem (tf32-rounded) ----
        {
            const float* kb = qkv + (size_t)(b * SEQ + tk * KTILE + lr) * QKVCOLS + DIM + h * HDIM;
            const float* vb = kb + DIM;
#pragma unroll
            for (int k = 0; k < 4; k++) {
                int c = lc + 16 * k;
                float4 kv = *(const float4*)(kb + c);
                float4 vv = *(const float4*)(vb + c);
                uint4 ko, vo;
                ko.x = f2tf32(kv.x); ko.y = f2tf32(kv.y); ko.z = f2tf32(kv.z); ko.w = f2tf32(kv.w);
                vo.x = f2tf32(vv.x); vo.y = f2tf32(vv.y); vo.z = f2tf32(vv.z); vo.w = f2tf32(vv.w);
                *(uint4*)&Ks[lr * LDK + c] = ko;
                *(uint4*)&Vs[lr * LDK + c] = vo;
            }
        }
        __syncthreads();

        // ---- S = Q K^T : 8 n-tiles x 8 k-steps ----
        float s[8][4];
#pragma unroll
        for (int nt = 0; nt < 8; nt++)
#pragma unroll
            for (int c = 0; c < 4; c++) s[nt][c] = 0.f;

        const uint32_t* Kb = (const uint32_t*)Ks;
#pragma unroll
        for (int kk = 0; kk < 8; kk++) {
#pragma unroll
            for (int nt = 0; nt < 8; nt++) {
                uint32_t bfr[2];
                bfr[0] = Kb[(nt * 8 + g) * LDK + kk * 8 + t];
                bfr[1] = Kb[(nt * 8 + g) * LDK + kk * 8 + t + 4];
                mma_tf32(s[nt], qa[kk], bfr);
            }
        }

        // ---- bias + running softmax ----
        float mt0 = -CUDART_INF_F, mt1 = -CUDART_INF_F;
        const int jbase = tk * KTILE + 2 * t;
#pragma unroll
        for (int nt = 0; nt < 8; nt++) {
            int j0 = jbase + nt * 8;
            int j1 = j0 + 1;
            int j0hi = j0 >> 5, j0lo = j0 & 31;
            int j1hi = j1 >> 5, j1lo = j1 & 31;
            s[nt][0] += __ldg(btab + ((i0hi - j0hi + 31) * 63 + (i0lo - j0lo + 31)) * HEADS);
            s[nt][1] += __ldg(btab + ((i0hi - j1hi + 31) * 63 + (i0lo - j1lo + 31)) * HEADS);
            s[nt][2] += __ldg(btab + ((i1hi - j0hi + 31) * 63 + (i1lo - j0lo + 31)) * HEADS);
            s[nt][3] += __ldg(btab + ((i1hi - j1hi + 31) * 63 + (i1lo - j1lo + 31)) * HEADS);
            mt0 = fmaxf(mt0, fmaxf(s[nt][0], s[nt][1]));
            mt1 = fmaxf(mt1, fmaxf(s[nt][2], s[nt][3]));
        }
        mt0 = fmaxf(mt0, __shfl_xor_sync(0xffffffffu, mt0, 1));
        mt0 = fmaxf(mt0, __shfl_xor_sync(0xffffffffu, mt0, 2));
        mt1 = fmaxf(mt1, __shfl_xor_sync(0xffffffffu, mt1, 1));
        mt1 = fmaxf(mt1, __shfl_xor_sync(0xffffffffu, mt1, 2));

        float mn0 = fmaxf(m0, mt0);
        float mn1 = fmaxf(m1, mt1);
        float a0 = __expf(m0 - mn0);
        float a1 = __expf(m1 - mn1);
        m0 = mn0; m1 = mn1;

        float ls0 = 0.f, ls1 = 0.f;
#pragma unroll
        for (int nt = 0; nt < 8; nt++) {
            float p00 = __expf(s[nt][0] - mn0);
            float p01 = __expf(s[nt][1] - mn0);
            float p10 = __expf(s[nt][2] - mn1);
            float p11 = __expf(s[nt][3] - mn1);
            ls0 += p00 + p01;
            ls1 += p10 + p11;
            float2 w0, w1;
            w0.x = __uint_as_float(f2tf32(p00));
            w0.y = __uint_as_float(f2tf32(p01));
            w1.x = __uint_as_float(f2tf32(p10));
            w1.y = __uint_as_float(f2tf32(p11));
            *(float2*)&Pw[g * LDK + nt * 8 + 2 * t]       = w0;
            *(float2*)&Pw[(g + 8) * LDK + nt * 8 + 2 * t] = w1;
        }
        ls0 += __shfl_xor_sync(0xffffffffu, ls0, 1);
        ls0 += __shfl_xor_sync(0xffffffffu, ls0, 2);
        ls1 += __shfl_xor_sync(0xffffffffu, ls1, 1);
        ls1 += __shfl_xor_sync(0xffffffffu, ls1, 2);
        l0 = l0 * a0 + ls0;
        l1 = l1 * a1 + ls1;

#pragma unroll
        for (int nt = 0; nt < 8; nt++) {
            o[nt][0] *= a0; o[nt][1] *= a0;
            o[nt][2] *= a1; o[nt][3] *= a1;
        }
        __syncwarp();

        // ---- O += P V : 8 k-steps (keys) x 8 n-tiles (dims) ----
        const uint32_t* Pb = (const uint32_t*)Pw;
        const uint32_t* Vb = (const uint32_t*)Vs;
#pragma unroll
        for (int kk = 0; kk < 8; kk++) {
            uint32_t afr[4];
            afr[0] = Pb[g * LDK + kk * 8 + t];
            afr[1] = Pb[(g + 8) * LDK + kk * 8 + t];
            afr[2] = Pb[g * LDK + kk * 8 + t + 4];
            afr[3] = Pb[(g + 8) * LDK + kk * 8 + t + 4];
#pragma unroll
            for (int nt = 0; nt < 8; nt++) {
                uint32_t bfr[2];
                bfr[0] = Vb[(kk * 8 + t) * LDK + nt * 8 + g];
                bfr[1] = Vb[(kk * 8 + t + 4) * LDK + nt * 8 + g];
                mma_tf32(o[nt], afr, bfr);
            }
        }
        __syncwarp();
    }

    // ---- normalize and write ctx ----
    float inv0 = 1.f / l0;
    float inv1 = 1.f / l1;
    const int orow0 = b * SEQ + r0 + wid * 16 + g;
    float* ob0 = ctx + (size_t)orow0 * DIM + h * HDIM + 2 * t;
    float* ob1 = ctx + (size_t)(orow0 + 8) * DIM + h * HDIM + 2 * t;
#pragma unroll
    for (int nt = 0; nt < 8; nt++) {
        float2 v0, v1;
        v0.x = o[nt][0] * inv0; v0.y = o[nt][1] * inv0;
        v1.x = o[nt][2] * inv1; v1.y = o[nt][3] * inv1;
        *(float2*)(ob0 + nt * 8) = v0;
        *(float2*)(ob1 + nt * 8) = v1;
    }
}

// ---------------------------------------------------------------------------
extern "C" void kernel_launch(void* const* d_in, const int* in_sizes, int n_in,
                              void* d_out, int out_size)
{
    const float* x          = (const float*)d_in[0];
    const float* qkv_w      = (const float*)d_in[1];
    const float* proj_w     = (const float*)d_in[2];
    const float* proj_b     = (const float*)d_in[3];
    const float* bias_table = (const float*)d_in[4];
    // d_in[5] = rel_index (int32) — computed analytically, unused
    float* out = (float*)d_out;

    float *qkv_s, *ctx_s;
    cudaGetSymbolAddress((void**)&qkv_s, g_qkv);
    cudaGetSymbolAddress((void**)&ctx_s, g_ctx);

    // 1) qkv = x @ qkv_w
    {
        dim3 grid(QKVCOLS / 128, ROWS / 128);
        sgemm128<<<grid, 256>>>(x, qkv_w, nullptr, qkv_s, ROWS, QKVCOLS, DIM);
    }

    // 2) flash attention (tf32 tensor cores)
    {
        cudaFuncSetAttribute(flash_attn_tc, cudaFuncAttributeMaxDynamicSharedMemorySize, FA_SMEM);
        dim3 grid(SEQ / QTILE, BATCH * HEADS);
        flash_attn_tc<<<grid, 256, FA_SMEM>>>(qkv_s, bias_table, ctx_s);
    }

    // 3) out = ctx @ proj_w + proj_b
    {
        dim3 grid(DIM / 128, ROWS / 128);
        sgemm128<<<grid, 256>>>(ctx_s, proj_w, proj_b, out, ROWS, DIM, DIM);
    }
}

// round 6
// speedup vs baseline: 4.2747x; 1.7549x over previous
#include <cuda_runtime.h>
#include <cuda_bf16.h>
#include <math_constants.h>
#include <cstdint>

// ---------------------------------------------------------------------------
// RelativeAttention: B=8, N=1024, C=768, H=12, hd=64, MAX_DIST=32
//   qkv = x @ qkv_w                      [8192, 2304]   (tf32 mma GEMM)
//   per (b,h): attn = softmax(q k^T * 0.125 + bias), ctx = attn @ v
//              (tf32 mma.sync flash attention)
//   out = ctx @ proj_w + proj_b          [8192, 768]    (tf32 mma GEMM)
// rel_index is analytic: idx = ((i>>5)-(j>>5)+31)*63 + ((i&31)-(j&31)+31)
// ---------------------------------------------------------------------------

#define BATCH   8
#define SEQ     1024
#define DIM     768
#define HEADS   12
#define HDIM    64
#define ROWS    (BATCH * SEQ)       // 8192
#define QKVCOLS (3 * DIM)           // 2304

// scratch (device globals: allocation-free)
__device__ float g_qkv[ROWS * QKVCOLS];   // ~75.5 MB
__device__ float g_ctx[ROWS * DIM];       // ~25.2 MB

// ---------------------------------------------------------------------------
// tf32 helpers
// ---------------------------------------------------------------------------
__device__ __forceinline__ uint32_t f2tf32(float x) {
    uint32_t r;
    asm("cvt.rna.tf32.f32 %0, %1;" : "=r"(r) : "f"(x));
    return r;
}

__device__ __forceinline__ void mma_tf32(float c[4], const uint32_t a[4], const uint32_t b[2]) {
    asm volatile(
        "mma.sync.aligned.m16n8k8.row.col.f32.tf32.tf32.f32 "
        "{%0,%1,%2,%3}, {%4,%5,%6,%7}, {%8,%9}, {%0,%1,%2,%3};\n"
        : "+f"(c[0]), "+f"(c[1]), "+f"(c[2]), "+f"(c[3])
        : "r"(a[0]), "r"(a[1]), "r"(a[2]), "r"(a[3]), "r"(b[0]), "r"(b[1]));
}

// ---------------------------------------------------------------------------
// tf32 tensor-core GEMM: C[M,N] = A[M,K] @ B[K,N] (+ bias[N])
// 128x128 block, BK=16, 256 threads (8 warps, 4x2), warp tile 32x64.
// As [m][k] pad 20 (fragment reads conflict-free), Bs [k][n] pad 136.
// Requires M%128==0, N%128==0, K%16==0.
// ---------------------------------------------------------------------------
#define GBK  16
#define LDA  20
#define LDB  136

__global__ __launch_bounds__(256, 2)
void tgemm128(const float* __restrict__ A, const float* __restrict__ B,
              const float* __restrict__ bias, float* __restrict__ C,
              int M, int N, int K)
{
    __shared__ uint32_t As[128 * LDA];   // [m][k]
    __shared__ uint32_t Bs[GBK * LDB];   // [k][n]

    const int tid  = threadIdx.x;
    const int wid  = tid >> 5;
    const int lane = tid & 31;
    const int g    = lane >> 2;     // 0..7
    const int t    = lane & 3;      // 0..3

    const int bm = blockIdx.y * 128;
    const int bn = blockIdx.x * 128;

    const int warp_m = (wid & 3) * 32;   // 0,32,64,96
    const int warp_n = (wid >> 2) * 64;  // 0,64

    const int a_row = tid >> 2;          // 0..63
    const int a_col = (tid & 3) * 4;     // 0,4,8,12
    const int b_row = tid >> 5;          // 0..7
    const int b_col = (tid & 31) * 4;    // 0..124

    float acc[2][8][4];
#pragma unroll
    for (int mi = 0; mi < 2; mi++)
#pragma unroll
        for (int ni = 0; ni < 8; ni++)
#pragma unroll
            for (int c = 0; c < 4; c++) acc[mi][ni][c] = 0.f;

    const float* Ab = A + (size_t)bm * K;
    const float* Bb = B + bn;

    // prefetch tile 0
    float4 pa0 = *(const float4*)(Ab + (size_t)a_row        * K + a_col);
    float4 pa1 = *(const float4*)(Ab + (size_t)(a_row + 64) * K + a_col);
    float4 pb0 = *(const float4*)(Bb + (size_t)b_row       * N + b_col);
    float4 pb1 = *(const float4*)(Bb + (size_t)(b_row + 8) * N + b_col);

    for (int k0 = 0; k0 < K; k0 += GBK) {
        // ---- stage prefetched tile into smem (tf32-rounded) ----
        {
            uint4 u;
            u.x = f2tf32(pa0.x); u.y = f2tf32(pa0.y); u.z = f2tf32(pa0.z); u.w = f2tf32(pa0.w);
            *(uint4*)&As[a_row * LDA + a_col] = u;
            u.x = f2tf32(pa1.x); u.y = f2tf32(pa1.y); u.z = f2tf32(pa1.z); u.w = f2tf32(pa1.w);
            *(uint4*)&As[(a_row + 64) * LDA + a_col] = u;
            u.x = f2tf32(pb0.x); u.y = f2tf32(pb0.y); u.z = f2tf32(pb0.z); u.w = f2tf32(pb0.w);
            *(uint4*)&Bs[b_row * LDB + b_col] = u;
            u.x = f2tf32(pb1.x); u.y = f2tf32(pb1.y); u.z = f2tf32(pb1.z); u.w = f2tf32(pb1.w);
            *(uint4*)&Bs[(b_row + 8) * LDB + b_col] = u;
        }
        __syncthreads();

        // ---- prefetch next tile ----
        if (k0 + GBK < K) {
            pa0 = *(const float4*)(Ab + (size_t)a_row        * K + k0 + GBK + a_col);
            pa1 = *(const float4*)(Ab + (size_t)(a_row + 64) * K + k0 + GBK + a_col);
            pb0 = *(const float4*)(Bb + (size_t)(k0 + GBK + b_row)     * N + b_col);
            pb1 = *(const float4*)(Bb + (size_t)(k0 + GBK + b_row + 8) * N + b_col);
        }

        // ---- compute: 2 k8-steps x (2 m-tiles x 8 n-tiles) ----
#pragma unroll
        for (int kk = 0; kk < 2; kk++) {
            uint32_t af[2][4];
#pragma unroll
            for (int mi = 0; mi < 2; mi++) {
                const int mr = warp_m + mi * 16;
                af[mi][0] = As[(mr + g)     * LDA + kk * 8 + t];
                af[mi][1] = As[(mr + g + 8) * LDA + kk * 8 + t];
                af[mi][2] = As[(mr + g)     * LDA + kk * 8 + t + 4];
                af[mi][3] = As[(mr + g + 8) * LDA + kk * 8 + t + 4];
            }
#pragma unroll
            for (int ni = 0; ni < 8; ni++) {
                uint32_t bf[2];
                bf[0] = Bs[(kk * 8 + t)     * LDB + warp_n + ni * 8 + g];
                bf[1] = Bs[(kk * 8 + t + 4) * LDB + warp_n + ni * 8 + g];
                mma_tf32(acc[0][ni], af[0], bf);
                mma_tf32(acc[1][ni], af[1], bf);
            }
        }
        __syncthreads();
    }

    // ---- epilogue: c0=(g,2t) c1=(g,2t+1) c2=(g+8,2t) c3=(g+8,2t+1) ----
#pragma unroll
    for (int mi = 0; mi < 2; mi++) {
        const int r0 = bm + warp_m + mi * 16 + g;
        float* cr0 = C + (size_t)r0 * N + bn;
        float* cr1 = cr0 + (size_t)8 * N;
#pragma unroll
        for (int ni = 0; ni < 8; ni++) {
            const int cc = warp_n + ni * 8 + 2 * t;
            float bx = 0.f, by = 0.f;
            if (bias) {
                bx = __ldg(&bias[bn + cc]);
                by = __ldg(&bias[bn + cc + 1]);
            }
            float2 v0, v1;
            v0.x = acc[mi][ni][0] + bx; v0.y = acc[mi][ni][1] + by;
            v1.x = acc[mi][ni][2] + bx; v1.y = acc[mi][ni][3] + by;
            *(float2*)(cr0 + cc) = v0;
            *(float2*)(cr1 + cc) = v1;
        }
    }
}

// ---------------------------------------------------------------------------
// Flash attention with relative bias, tf32 tensor cores.
// grid = (SEQ/128, B*H); block = 256 (8 warps). Each warp: 16 query rows.
// ---------------------------------------------------------------------------
#define QTILE 128
#define KTILE 64
#define LDK   68
#define FA_SMEM ((2 * 64 * LDK + 8 * 16 * LDK) * 4)

__global__ __launch_bounds__(256)
void flash_attn_tc(const float* __restrict__ qkv,
                   const float* __restrict__ bias_table,
                   float* __restrict__ ctx)
{
    extern __shared__ float sm[];
    float* Ks = sm;                    // 64 x 68 (tf32 bits)
    float* Vs = Ks + 64 * LDK;         // 64 x 68 (tf32 bits)
    float* Ps = Vs + 64 * LDK;         // 8 warps x 16 x 68

    const int bh = blockIdx.y;
    const int b  = bh / HEADS;
    const int h  = bh % HEADS;
    const int r0 = blockIdx.x * QTILE;

    const int tid  = threadIdx.x;
    const int wid  = tid >> 5;
    const int lane = tid & 31;
    const int g    = lane >> 2;     // 0..7
    const int t    = lane & 3;      // 0..3

    float* Pw = Ps + wid * 16 * LDK;

    // ---- load Q A-fragments (16 rows per warp), scaled, tf32 ----
    uint32_t qa[8][4];
    {
        const int qr0 = b * SEQ + r0 + wid * 16;
        const float* qb = qkv + (size_t)qr0 * QKVCOLS + h * HDIM;
#pragma unroll
        for (int kk = 0; kk < 8; kk++) {
            qa[kk][0] = f2tf32(0.125f * __ldg(qb + (size_t)g       * QKVCOLS + kk * 8 + t));
            qa[kk][1] = f2tf32(0.125f * __ldg(qb + (size_t)(g + 8) * QKVCOLS + kk * 8 + t));
            qa[kk][2] = f2tf32(0.125f * __ldg(qb + (size_t)g       * QKVCOLS + kk * 8 + t + 4));
            qa[kk][3] = f2tf32(0.125f * __ldg(qb + (size_t)(g + 8) * QKVCOLS + kk * 8 + t + 4));
        }
    }

    float o[8][4];
#pragma unroll
    for (int nt = 0; nt < 8; nt++)
#pragma unroll
        for (int c = 0; c < 4; c++) o[nt][c] = 0.f;

    float m0 = -CUDART_INF_F, m1 = -CUDART_INF_F;
    float l0 = 0.f, l1 = 0.f;

    const int i0 = r0 + wid * 16 + g;
    const int i1 = i0 + 8;
    const int i0hi = i0 >> 5, i0lo = i0 & 31;
    const int i1hi = i1 >> 5, i1lo = i1 & 31;
    const float* btab = bias_table + h;

    const int lr = tid >> 2;        // 0..63 (K/V tile loader row)
    const int lc = (tid & 3) * 4;   // base float4 col

    for (int tk = 0; tk < SEQ / KTILE; tk++) {
        __syncthreads();
        // ---- stage K,V tile into smem (tf32-rounded) ----
        {
            const float* kb = qkv + (size_t)(b * SEQ + tk * KTILE + lr) * QKVCOLS + DIM + h * HDIM;
            const float* vb = kb + DIM;
#pragma unroll
            for (int k = 0; k < 4; k++) {
                int c = lc + 16 * k;
                float4 kv = *(const float4*)(kb + c);
                float4 vv = *(const float4*)(vb + c);
                uint4 ko, vo;
                ko.x = f2tf32(kv.x); ko.y = f2tf32(kv.y); ko.z = f2tf32(kv.z); ko.w = f2tf32(kv.w);
                vo.x = f2tf32(vv.x); vo.y = f2tf32(vv.y); vo.z = f2tf32(vv.z); vo.w = f2tf32(vv.w);
                *(uint4*)&Ks[lr * LDK + c] = ko;
                *(uint4*)&Vs[lr * LDK + c] = vo;
            }
        }
        __syncthreads();

        // ---- S = Q K^T ----
        float s[8][4];
#pragma unroll
        for (int nt = 0; nt < 8; nt++)
#pragma unroll
            for (int c = 0; c < 4; c++) s[nt][c] = 0.f;

        const uint32_t* Kb = (const uint32_t*)Ks;
#pragma unroll
        for (int kk = 0; kk < 8; kk++) {
#pragma unroll
            for (int nt = 0; nt < 8; nt++) {
                uint32_t bfr[2];
                bfr[0] = Kb[(nt * 8 + g) * LDK + kk * 8 + t];
                bfr[1] = Kb[(nt * 8 + g) * LDK + kk * 8 + t + 4];
                mma_tf32(s[nt], qa[kk], bfr);
            }
        }

        // ---- bias + running softmax ----
        float mt0 = -CUDART_INF_F, mt1 = -CUDART_INF_F;
        const int jbase = tk * KTILE + 2 * t;
#pragma unroll
        for (int nt = 0; nt < 8; nt++) {
            int j0 = jbase + nt * 8;
            int j1 = j0 + 1;
            int j0hi = j0 >> 5, j0lo = j0 & 31;
            int j1hi = j1 >> 5, j1lo = j1 & 31;
            s[nt][0] += __ldg(btab + ((i0hi - j0hi + 31) * 63 + (i0lo - j0lo + 31)) * HEADS);
            s[nt][1] += __ldg(btab + ((i0hi - j1hi + 31) * 63 + (i0lo - j1lo + 31)) * HEADS);
            s[nt][2] += __ldg(btab + ((i1hi - j0hi + 31) * 63 + (i1lo - j0lo + 31)) * HEADS);
            s[nt][3] += __ldg(btab + ((i1hi - j1hi + 31) * 63 + (i1lo - j1lo + 31)) * HEADS);
            mt0 = fmaxf(mt0, fmaxf(s[nt][0], s[nt][1]));
            mt1 = fmaxf(mt1, fmaxf(s[nt][2], s[nt][3]));
        }
        mt0 = fmaxf(mt0, __shfl_xor_sync(0xffffffffu, mt0, 1));
        mt0 = fmaxf(mt0, __shfl_xor_sync(0xffffffffu, mt0, 2));
        mt1 = fmaxf(mt1, __shfl_xor_sync(0xffffffffu, mt1, 1));
        mt1 = fmaxf(mt1, __shfl_xor_sync(0xffffffffu, mt1, 2));

        float mn0 = fmaxf(m0, mt0);
        float mn1 = fmaxf(m1, mt1);
        float a0 = __expf(m0 - mn0);
        float a1 = __expf(m1 - mn1);
        m0 = mn0; m1 = mn1;

        float ls0 = 0.f, ls1 = 0.f;
#pragma unroll
        for (int nt = 0; nt < 8; nt++) {
            float p00 = __expf(s[nt][0] - mn0);
            float p01 = __expf(s[nt][1] - mn0);
            float p10 = __expf(s[nt][2] - mn1);
            float p11 = __expf(s[nt][3] - mn1);
            ls0 += p00 + p01;
            ls1 += p10 + p11;
            float2 w0, w1;
            w0.x = __uint_as_float(f2tf32(p00));
            w0.y = __uint_as_float(f2tf32(p01));
            w1.x = __uint_as_float(f2tf32(p10));
            w1.y = __uint_as_float(f2tf32(p11));
            *(float2*)&Pw[g * LDK + nt * 8 + 2 * t]       = w0;
            *(float2*)&Pw[(g + 8) * LDK + nt * 8 + 2 * t] = w1;
        }
        ls0 += __shfl_xor_sync(0xffffffffu, ls0, 1);
        ls0 += __shfl_xor_sync(0xffffffffu, ls0, 2);
        ls1 += __shfl_xor_sync(0xffffffffu, ls1, 1);
        ls1 += __shfl_xor_sync(0xffffffffu, ls1, 2);
        l0 = l0 * a0 + ls0;
        l1 = l1 * a1 + ls1;

#pragma unroll
        for (int nt = 0; nt < 8; nt++) {
            o[nt][0] *= a0; o[nt][1] *= a0;
            o[nt][2] *= a1; o[nt][3] *= a1;
        }
        __syncwarp();

        // ---- O += P V ----
        const uint32_t* Pb = (const uint32_t*)Pw;
        const uint32_t* Vb = (const uint32_t*)Vs;
#pragma unroll
        for (int kk = 0; kk < 8; kk++) {
            uint32_t afr[4];
            afr[0] = Pb[g * LDK + kk * 8 + t];
            afr[1] = Pb[(g + 8) * LDK + kk * 8 + t];
            afr[2] = Pb[g * LDK + kk * 8 + t + 4];
            afr[3] = Pb[(g + 8) * LDK + kk * 8 + t + 4];
#pragma unroll
            for (int nt = 0; nt < 8; nt++) {
                uint32_t bfr[2];
                bfr[0] = Vb[(kk * 8 + t) * LDK + nt * 8 + g];
                bfr[1] = Vb[(kk * 8 + t + 4) * LDK + nt * 8 + g];
                mma_tf32(o[nt], afr, bfr);
            }
        }
        __syncwarp();
    }

    // ---- normalize and write ctx ----
    float inv0 = 1.f / l0;
    float inv1 = 1.f / l1;
    const int orow0 = b * SEQ + r0 + wid * 16 + g;
    float* ob0 = ctx + (size_t)orow0 * DIM + h * HDIM + 2 * t;
    float* ob1 = ctx + (size_t)(orow0 + 8) * DIM + h * HDIM + 2 * t;
#pragma unroll
    for (int nt = 0; nt < 8; nt++) {
        float2 v0, v1;
        v0.x = o[nt][0] * inv0; v0.y = o[nt][1] * inv0;
        v1.x = o[nt][2] * inv1; v1.y = o[nt][3] * inv1;
        *(float2*)(ob0 + nt * 8) = v0;
        *(float2*)(ob1 + nt * 8) = v1;
    }
}

// ---------------------------------------------------------------------------
extern "C" void kernel_launch(void* const* d_in, const int* in_sizes, int n_in,
                              void* d_out, int out_size)
{
    const float* x          = (const float*)d_in[0];
    const float* qkv_w      = (const float*)d_in[1];
    const float* proj_w     = (const float*)d_in[2];
    const float* proj_b     = (const float*)d_in[3];
    const float* bias_table = (const float*)d_in[4];
    // d_in[5] = rel_index (int32) — computed analytically, unused
    float* out = (float*)d_out;

    float *qkv_s, *ctx_s;
    cudaGetSymbolAddress((void**)&qkv_s, g_qkv);
    cudaGetSymbolAddress((void**)&ctx_s, g_ctx);

    // 1) qkv = x @ qkv_w  (tf32 tensor cores)
    {
        dim3 grid(QKVCOLS / 128, ROWS / 128);
        tgemm128<<<grid, 256>>>(x, qkv_w, nullptr, qkv_s, ROWS, QKVCOLS, DIM);
    }

    // 2) flash attention (tf32 tensor cores)
    {
        cudaFuncSetAttribute(flash_attn_tc, cudaFuncAttributeMaxDynamicSharedMemorySize, FA_SMEM);
        dim3 grid(SEQ / QTILE, BATCH * HEADS);
        flash_attn_tc<<<grid, 256, FA_SMEM>>>(qkv_s, bias_table, ctx_s);
    }

    // 3) out = ctx @ proj_w + proj_b  (tf32 tensor cores)
    {
        dim3 grid(DIM / 128, ROWS / 128);
        tgemm128<<<grid, 256>>>(ctx_s, proj_w, proj_b, out, ROWS, DIM, DIM);
    }
}

// round 7
// speedup vs baseline: 4.9709x; 1.1629x over previous
#include <cuda_runtime.h>
#include <cuda_bf16.h>
#include <math_constants.h>
#include <cstdint>

// ---------------------------------------------------------------------------
// RelativeAttention: B=8, N=1024, C=768, H=12, hd=64, MAX_DIST=32
//   qkv = x @ qkv_w                      [8192, 2304]   (tf32 mma GEMM)
//   per (b,h): attn = softmax(q k^T * 0.125 + bias), ctx = attn @ v
//              (tf32 mma flash attention, bias staged in smem, exp2 domain)
//   out = ctx @ proj_w + proj_b          [8192, 768]    (tf32 mma GEMM)
// rel_index is analytic: idx = ((i>>5)-(j>>5)+31)*63 + ((i&31)-(j&31)+31)
// ---------------------------------------------------------------------------

#define BATCH   8
#define SEQ     1024
#define DIM     768
#define HEADS   12
#define HDIM    64
#define ROWS    (BATCH * SEQ)       // 8192
#define QKVCOLS (3 * DIM)           // 2304
#define LOG2E   1.4426950408889634f

// scratch (device globals: allocation-free)
__device__ float g_qkv[ROWS * QKVCOLS];   // ~75.5 MB
__device__ float g_ctx[ROWS * DIM];       // ~25.2 MB

// ---------------------------------------------------------------------------
// tf32 helpers
// ---------------------------------------------------------------------------
__device__ __forceinline__ uint32_t f2tf32(float x) {
    uint32_t r;
    asm("cvt.rna.tf32.f32 %0, %1;" : "=r"(r) : "f"(x));
    return r;
}

__device__ __forceinline__ void mma_tf32(float c[4], const uint32_t a[4], const uint32_t b[2]) {
    asm volatile(
        "mma.sync.aligned.m16n8k8.row.col.f32.tf32.tf32.f32 "
        "{%0,%1,%2,%3}, {%4,%5,%6,%7}, {%8,%9}, {%0,%1,%2,%3};\n"
        : "+f"(c[0]), "+f"(c[1]), "+f"(c[2]), "+f"(c[3])
        : "r"(a[0]), "r"(a[1]), "r"(a[2]), "r"(a[3]), "r"(b[0]), "r"(b[1]));
}

// ---------------------------------------------------------------------------
// tf32 tensor-core GEMM: C[M,N] = A[M,K] @ B[K,N] (+ bias[N])
// 128x128 block, BK=16, 256 threads (8 warps, 4x2), warp tile 32x64.
// ---------------------------------------------------------------------------
#define GBK  16
#define LDA  20
#define LDB  136

__global__ __launch_bounds__(256, 2)
void tgemm128(const float* __restrict__ A, const float* __restrict__ B,
              const float* __restrict__ bias, float* __restrict__ C,
              int M, int N, int K)
{
    __shared__ uint32_t As[128 * LDA];   // [m][k]
    __shared__ uint32_t Bs[GBK * LDB];   // [k][n]

    const int tid  = threadIdx.x;
    const int wid  = tid >> 5;
    const int lane = tid & 31;
    const int g    = lane >> 2;     // 0..7
    const int t    = lane & 3;      // 0..3

    const int bm = blockIdx.y * 128;
    const int bn = blockIdx.x * 128;

    const int warp_m = (wid & 3) * 32;   // 0,32,64,96
    const int warp_n = (wid >> 2) * 64;  // 0,64

    const int a_row = tid >> 2;          // 0..63
    const int a_col = (tid & 3) * 4;     // 0,4,8,12
    const int b_row = tid >> 5;          // 0..7
    const int b_col = (tid & 31) * 4;    // 0..124

    float acc[2][8][4];
#pragma unroll
    for (int mi = 0; mi < 2; mi++)
#pragma unroll
        for (int ni = 0; ni < 8; ni++)
#pragma unroll
            for (int c = 0; c < 4; c++) acc[mi][ni][c] = 0.f;

    const float* Ab = A + (size_t)bm * K;
    const float* Bb = B + bn;

    // prefetch tile 0
    float4 pa0 = *(const float4*)(Ab + (size_t)a_row        * K + a_col);
    float4 pa1 = *(const float4*)(Ab + (size_t)(a_row + 64) * K + a_col);
    float4 pb0 = *(const float4*)(Bb + (size_t)b_row       * N + b_col);
    float4 pb1 = *(const float4*)(Bb + (size_t)(b_row + 8) * N + b_col);

    for (int k0 = 0; k0 < K; k0 += GBK) {
        {
            uint4 u;
            u.x = f2tf32(pa0.x); u.y = f2tf32(pa0.y); u.z = f2tf32(pa0.z); u.w = f2tf32(pa0.w);
            *(uint4*)&As[a_row * LDA + a_col] = u;
            u.x = f2tf32(pa1.x); u.y = f2tf32(pa1.y); u.z = f2tf32(pa1.z); u.w = f2tf32(pa1.w);
            *(uint4*)&As[(a_row + 64) * LDA + a_col] = u;
            u.x = f2tf32(pb0.x); u.y = f2tf32(pb0.y); u.z = f2tf32(pb0.z); u.w = f2tf32(pb0.w);
            *(uint4*)&Bs[b_row * LDB + b_col] = u;
            u.x = f2tf32(pb1.x); u.y = f2tf32(pb1.y); u.z = f2tf32(pb1.z); u.w = f2tf32(pb1.w);
            *(uint4*)&Bs[(b_row + 8) * LDB + b_col] = u;
        }
        __syncthreads();

        if (k0 + GBK < K) {
            pa0 = *(const float4*)(Ab + (size_t)a_row        * K + k0 + GBK + a_col);
            pa1 = *(const float4*)(Ab + (size_t)(a_row + 64) * K + k0 + GBK + a_col);
            pb0 = *(const float4*)(Bb + (size_t)(k0 + GBK + b_row)     * N + b_col);
            pb1 = *(const float4*)(Bb + (size_t)(k0 + GBK + b_row + 8) * N + b_col);
        }

#pragma unroll
        for (int kk = 0; kk < 2; kk++) {
            uint32_t af[2][4];
#pragma unroll
            for (int mi = 0; mi < 2; mi++) {
                const int mr = warp_m + mi * 16;
                af[mi][0] = As[(mr + g)     * LDA + kk * 8 + t];
                af[mi][1] = As[(mr + g + 8) * LDA + kk * 8 + t];
                af[mi][2] = As[(mr + g)     * LDA + kk * 8 + t + 4];
                af[mi][3] = As[(mr + g + 8) * LDA + kk * 8 + t + 4];
            }
#pragma unroll
            for (int ni = 0; ni < 8; ni++) {
                uint32_t bf[2];
                bf[0] = Bs[(kk * 8 + t)     * LDB + warp_n + ni * 8 + g];
                bf[1] = Bs[(kk * 8 + t + 4) * LDB + warp_n + ni * 8 + g];
                mma_tf32(acc[0][ni], af[0], bf);
                mma_tf32(acc[1][ni], af[1], bf);
            }
        }
        __syncthreads();
    }

#pragma unroll
    for (int mi = 0; mi < 2; mi++) {
        const int r0 = bm + warp_m + mi * 16 + g;
        float* cr0 = C + (size_t)r0 * N + bn;
        float* cr1 = cr0 + (size_t)8 * N;
#pragma unroll
        for (int ni = 0; ni < 8; ni++) {
            const int cc = warp_n + ni * 8 + 2 * t;
            float bx = 0.f, by = 0.f;
            if (bias) {
                bx = __ldg(&bias[bn + cc]);
                by = __ldg(&bias[bn + cc + 1]);
            }
            float2 v0, v1;
            v0.x = acc[mi][ni][0] + bx; v0.y = acc[mi][ni][1] + by;
            v1.x = acc[mi][ni][2] + bx; v1.y = acc[mi][ni][3] + by;
            *(float2*)(cr0 + cc) = v0;
            *(float2*)(cr1 + cc) = v1;
        }
    }
}

// ---------------------------------------------------------------------------
// Flash attention, tf32 mma, bias via smem, softmax in exp2 domain.
// grid = (SEQ/128, B*H); block = 256 (8 warps), 16 query rows per warp.
// smem: Ks 64x68 | Vs 64x68 | Ps 8*(16x68) | Bt 63x64  = 85760 B
// ---------------------------------------------------------------------------
#define QTILE 128
#define KTILE 64
#define LDK   68
#define BT_ELEMS (63 * 64)
#define FA_SMEM ((2 * 64 * LDK + 8 * 16 * LDK + BT_ELEMS) * 4)

__global__ __launch_bounds__(256)
void flash_attn_tc(const float* __restrict__ qkv,
                   const float* __restrict__ bias_table,
                   float* __restrict__ ctx)
{
    extern __shared__ float sm[];
    float* Ks = sm;                    // 64 x 68 (tf32 bits)
    float* Vs = Ks + 64 * LDK;         // 64 x 68 (tf32 bits)
    float* Ps = Vs + 64 * LDK;         // 8 warps x 16 x 68
    float* Bt = Ps + 8 * 16 * LDK;     // 63 x 64 (per-head bias * log2e)

    const int bh = blockIdx.y;
    const int b  = bh / HEADS;
    const int h  = bh % HEADS;
    const int r0 = blockIdx.x * QTILE;

    const int tid  = threadIdx.x;
    const int wid  = tid >> 5;
    const int lane = tid & 31;
    const int g    = lane >> 2;     // 0..7
    const int t    = lane & 3;      // 0..3

    float* Pw = Ps + wid * 16 * LDK;

    // ---- stage per-head bias slice into smem, scaled by log2(e) ----
    for (int v = tid; v < 63 * 63; v += 256) {
        int r = v / 63, c = v - r * 63;
        Bt[r * 64 + c] = __ldg(&bias_table[v * HEADS + h]) * LOG2E;
    }

    // ---- load Q A-fragments (16 rows per warp), scale 0.125*log2e ----
    const float qscale = 0.125f * LOG2E;
    uint32_t qa[8][4];
    {
        const int qr0 = b * SEQ + r0 + wid * 16;
        const float* qb = qkv + (size_t)qr0 * QKVCOLS + h * HDIM;
#pragma unroll
        for (int kk = 0; kk < 8; kk++) {
            qa[kk][0] = f2tf32(qscale * __ldg(qb + (size_t)g       * QKVCOLS + kk * 8 + t));
            qa[kk][1] = f2tf32(qscale * __ldg(qb + (size_t)(g + 8) * QKVCOLS + kk * 8 + t));
            qa[kk][2] = f2tf32(qscale * __ldg(qb + (size_t)g       * QKVCOLS + kk * 8 + t + 4));
            qa[kk][3] = f2tf32(qscale * __ldg(qb + (size_t)(g + 8) * QKVCOLS + kk * 8 + t + 4));
        }
    }

    float o[8][4];
#pragma unroll
    for (int nt = 0; nt < 8; nt++)
#pragma unroll
        for (int c = 0; c < 4; c++) o[nt][c] = 0.f;

    float m0 = -CUDART_INF_F, m1 = -CUDART_INF_F;
    float l0 = 0.f, l1 = 0.f;

    // per-thread bias row constants: ci = (i>>5)*64 + (i&31) + 31*65
    const int i0 = r0 + wid * 16 + g;
    const int i1 = i0 + 8;
    const int ci0 = (i0 >> 5) * 64 + (i0 & 31) + 2015;
    const int ci1 = (i1 >> 5) * 64 + (i1 & 31) + 2015;

    const int lr = tid >> 2;        // 0..63 (K/V tile loader row)
    const int lc = (tid & 3) * 4;   // base float4 col

    for (int tk = 0; tk < SEQ / KTILE; tk++) {
        __syncthreads();
        // ---- stage K,V tile into smem (tf32-rounded) ----
        {
            const float* kb = qkv + (size_t)(b * SEQ + tk * KTILE + lr) * QKVCOLS + DIM + h * HDIM;
            const float* vb = kb + DIM;
#pragma unroll
            for (int k = 0; k < 4; k++) {
                int c = lc + 16 * k;
                float4 kv = *(const float4*)(kb + c);
                float4 vv = *(const float4*)(vb + c);
                uint4 ko, vo;
                ko.x = f2tf32(kv.x); ko.y = f2tf32(kv.y); ko.z = f2tf32(kv.z); ko.w = f2tf32(kv.w);
                vo.x = f2tf32(vv.x); vo.y = f2tf32(vv.y); vo.z = f2tf32(vv.z); vo.w = f2tf32(vv.w);
                *(uint4*)&Ks[lr * LDK + c] = ko;
                *(uint4*)&Vs[lr * LDK + c] = vo;
            }
        }
        __syncthreads();

        // ---- S = Q K^T (scores in log2 domain) ----
        float s[8][4];
#pragma unroll
        for (int nt = 0; nt < 8; nt++)
#pragma unroll
            for (int c = 0; c < 4; c++) s[nt][c] = 0.f;

        const uint32_t* Kb = (const uint32_t*)Ks;
#pragma unroll
        for (int kk = 0; kk < 8; kk++) {
#pragma unroll
            for (int nt = 0; nt < 8; nt++) {
                uint32_t bfr[2];
                bfr[0] = Kb[(nt * 8 + g) * LDK + kk * 8 + t];
                bfr[1] = Kb[(nt * 8 + g) * LDK + kk * 8 + t + 4];
                mma_tf32(s[nt], qa[kk], bfr);
            }
        }

        // ---- bias (smem) + running softmax (exp2 domain) ----
        float mt0 = -CUDART_INF_F, mt1 = -CUDART_INF_F;
        const int jbase = tk * KTILE + 2 * t;
#pragma unroll
        for (int nt = 0; nt < 8; nt++) {
            int j0 = jbase + nt * 8;
            int cj = j0 + (j0 & ~31);       // (j>>5)*64 + (j&31)
            s[nt][0] += Bt[ci0 - cj];
            s[nt][1] += Bt[ci0 - cj - 1];
            s[nt][2] += Bt[ci1 - cj];
            s[nt][3] += Bt[ci1 - cj - 1];
            mt0 = fmaxf(mt0, fmaxf(s[nt][0], s[nt][1]));
            mt1 = fmaxf(mt1, fmaxf(s[nt][2], s[nt][3]));
        }
        mt0 = fmaxf(mt0, __shfl_xor_sync(0xffffffffu, mt0, 1));
        mt0 = fmaxf(mt0, __shfl_xor_sync(0xffffffffu, mt0, 2));
        mt1 = fmaxf(mt1, __shfl_xor_sync(0xffffffffu, mt1, 1));
        mt1 = fmaxf(mt1, __shfl_xor_sync(0xffffffffu, mt1, 2));

        float mn0 = fmaxf(m0, mt0);
        float mn1 = fmaxf(m1, mt1);
        float a0 = exp2f(m0 - mn0);
        float a1 = exp2f(m1 - mn1);
        m0 = mn0; m1 = mn1;

        float ls0 = 0.f, ls1 = 0.f;
#pragma unroll
        for (int nt = 0; nt < 8; nt++) {
            float p00 = exp2f(s[nt][0] - mn0);
            float p01 = exp2f(s[nt][1] - mn0);
            float p10 = exp2f(s[nt][2] - mn1);
            float p11 = exp2f(s[nt][3] - mn1);
            ls0 += p00 + p01;
            ls1 += p10 + p11;
            float2 w0, w1;
            w0.x = __uint_as_float(f2tf32(p00));
            w0.y = __uint_as_float(f2tf32(p01));
            w1.x = __uint_as_float(f2tf32(p10));
            w1.y = __uint_as_float(f2tf32(p11));
            *(float2*)&Pw[g * LDK + nt * 8 + 2 * t]       = w0;
            *(float2*)&Pw[(g + 8) * LDK + nt * 8 + 2 * t] = w1;
        }
        ls0 += __shfl_xor_sync(0xffffffffu, ls0, 1);
        ls0 += __shfl_xor_sync(0xffffffffu, ls0, 2);
        ls1 += __shfl_xor_sync(0xffffffffu, ls1, 1);
        ls1 += __shfl_xor_sync(0xffffffffu, ls1, 2);
        l0 = l0 * a0 + ls0;
        l1 = l1 * a1 + ls1;

#pragma unroll
        for (int nt = 0; nt < 8; nt++) {
            o[nt][0] *= a0; o[nt][1] *= a0;
            o[nt][2] *= a1; o[nt][3] *= a1;
        }
        __syncwarp();

        // ---- O += P V ----
        const uint32_t* Pb = (const uint32_t*)Pw;
        const uint32_t* Vb = (const uint32_t*)Vs;
#pragma unroll
        for (int kk = 0; kk < 8; kk++) {
            uint32_t afr[4];
            afr[0] = Pb[g * LDK + kk * 8 + t];
            afr[1] = Pb[(g + 8) * LDK + kk * 8 + t];
            afr[2] = Pb[g * LDK + kk * 8 + t + 4];
            afr[3] = Pb[(g + 8) * LDK + kk * 8 + t + 4];
#pragma unroll
            for (int nt = 0; nt < 8; nt++) {
                uint32_t bfr[2];
                bfr[0] = Vb[(kk * 8 + t) * LDK + nt * 8 + g];
                bfr[1] = Vb[(kk * 8 + t + 4) * LDK + nt * 8 + g];
                mma_tf32(o[nt], afr, bfr);
            }
        }
        __syncwarp();
    }

    // ---- normalize and write ctx ----
    float inv0 = 1.f / l0;
    float inv1 = 1.f / l1;
    const int orow0 = b * SEQ + r0 + wid * 16 + g;
    float* ob0 = ctx + (size_t)orow0 * DIM + h * HDIM + 2 * t;
    float* ob1 = ctx + (size_t)(orow0 + 8) * DIM + h * HDIM + 2 * t;
#pragma unroll
    for (int nt = 0; nt < 8; nt++) {
        float2 v0, v1;
        v0.x = o[nt][0] * inv0; v0.y = o[nt][1] * inv0;
        v1.x = o[nt][2] * inv1; v1.y = o[nt][3] * inv1;
        *(float2*)(ob0 + nt * 8) = v0;
        *(float2*)(ob1 + nt * 8) = v1;
    }
}

// ---------------------------------------------------------------------------
extern "C" void kernel_launch(void* const* d_in, const int* in_sizes, int n_in,
                              void* d_out, int out_size)
{
    const float* x          = (const float*)d_in[0];
    const float* qkv_w      = (const float*)d_in[1];
    const float* proj_w     = (const float*)d_in[2];
    const float* proj_b     = (const float*)d_in[3];
    const float* bias_table = (const float*)d_in[4];
    // d_in[5] = rel_index (int32) — computed analytically, unused
    float* out = (float*)d_out;

    float *qkv_s, *ctx_s;
    cudaGetSymbolAddress((void**)&qkv_s, g_qkv);
    cudaGetSymbolAddress((void**)&ctx_s, g_ctx);

    // 1) qkv = x @ qkv_w  (tf32 tensor cores)
    {
        dim3 grid(QKVCOLS / 128, ROWS / 128);
        tgemm128<<<grid, 256>>>(x, qkv_w, nullptr, qkv_s, ROWS, QKVCOLS, DIM);
    }

    // 2) flash attention (tf32 tensor cores, smem bias)
    {
        cudaFuncSetAttribute(flash_attn_tc, cudaFuncAttributeMaxDynamicSharedMemorySize, FA_SMEM);
        dim3 grid(SEQ / QTILE, BATCH * HEADS);
        flash_attn_tc<<<grid, 256, FA_SMEM>>>(qkv_s, bias_table, ctx_s);
    }

    // 3) out = ctx @ proj_w + proj_b  (tf32 tensor cores)
    {
        dim3 grid(DIM / 128, ROWS / 128);
        tgemm128<<<grid, 256>>>(ctx_s, proj_w, proj_b, out, ROWS, DIM, DIM);
    }
}

// round 8
// speedup vs baseline: 5.5823x; 1.1230x over previous
#include <cuda_runtime.h>
#include <cuda_bf16.h>
#include <math_constants.h>
#include <cstdint>

// ---------------------------------------------------------------------------
// RelativeAttention: B=8, N=1024, C=768, H=12, hd=64, MAX_DIST=32
//   qkv = x @ qkv_w                      [8192, 2304]   (tf32 mma GEMM, cp.async)
//   per (b,h): attn = softmax(q k^T * 0.125 + bias), ctx = attn @ v
//              (tf32 mma flash attention, bias staged in smem, exp2 domain)
//   out = ctx @ proj_w + proj_b          [8192, 768]    (tf32 mma GEMM, cp.async)
// rel_index is analytic: idx = ((i>>5)-(j>>5)+31)*63 + ((i&31)-(j&31)+31)
// ---------------------------------------------------------------------------

#define BATCH   8
#define SEQ     1024
#define DIM     768
#define HEADS   12
#define HDIM    64
#define ROWS    (BATCH * SEQ)       // 8192
#define QKVCOLS (3 * DIM)           // 2304
#define LOG2E   1.4426950408889634f

// scratch (device globals: allocation-free)
__device__ float g_qkv[ROWS * QKVCOLS];   // ~75.5 MB
__device__ float g_ctx[ROWS * DIM];       // ~25.2 MB

// ---------------------------------------------------------------------------
// tf32 helpers
// ---------------------------------------------------------------------------
__device__ __forceinline__ uint32_t f2tf32(float x) {
    uint32_t r;
    asm("cvt.rna.tf32.f32 %0, %1;" : "=r"(r) : "f"(x));
    return r;
}

__device__ __forceinline__ void mma_tf32(float c[4], const uint32_t a[4], const uint32_t b[2]) {
    asm volatile(
        "mma.sync.aligned.m16n8k8.row.col.f32.tf32.tf32.f32 "
        "{%0,%1,%2,%3}, {%4,%5,%6,%7}, {%8,%9}, {%0,%1,%2,%3};\n"
        : "+f"(c[0]), "+f"(c[1]), "+f"(c[2]), "+f"(c[3])
        : "r"(a[0]), "r"(a[1]), "r"(a[2]), "r"(a[3]), "r"(b[0]), "r"(b[1]));
}

__device__ __forceinline__ void cp16(uint32_t smem_word_addr_bytes, const void* gptr) {
    asm volatile("cp.async.ca.shared.global [%0], [%1], 16;\n"
                 :: "r"(smem_word_addr_bytes), "l"(gptr));
}

// ---------------------------------------------------------------------------
// tf32 tensor-core GEMM, cp.async double-buffered.
// C[M,N] = A[M,K] @ B[K,N] (+ bias[N])
// Block 128x128, BK=16, 128 threads (4 warps, 2x2), warp tile 64x64.
// tf32 via HW truncation of fp32 bits (no cvt).
// Requires M%128==0, N%128==0, K%16==0.
// ---------------------------------------------------------------------------
#define GBK  16
#define LDA  20     // words per A row
#define LDB  136    // words per B row
#define ASTG (128 * LDA)   // 2560 words
#define BSTG (GBK * LDB)   // 2176 words

__global__ __launch_bounds__(128, 2)
void tgemm_db(const float* __restrict__ A, const float* __restrict__ B,
              const float* __restrict__ bias, float* __restrict__ C,
              int M, int N, int K)
{
    __shared__ __align__(16) uint32_t As[2][ASTG];   // [m][k]
    __shared__ __align__(16) uint32_t Bs[2][BSTG];   // [k][n]

    const int tid  = threadIdx.x;
    const int wid  = tid >> 5;
    const int lane = tid & 31;
    const int g    = lane >> 2;     // 0..7
    const int t    = lane & 3;      // 0..3

    const int bm = blockIdx.y * 128;
    const int bn = blockIdx.x * 128;

    const int warp_m = (wid & 1) * 64;
    const int warp_n = (wid >> 1) * 64;

    const float* Ab = A + (size_t)bm * K;
    const float* Bb = B + bn;

    const uint32_t as_base = (uint32_t)__cvta_generic_to_shared(&As[0][0]);
    const uint32_t bs_base = (uint32_t)__cvta_generic_to_shared(&Bs[0][0]);

    float acc[4][8][4];
#pragma unroll
    for (int mi = 0; mi < 4; mi++)
#pragma unroll
        for (int ni = 0; ni < 8; ni++)
#pragma unroll
            for (int c = 0; c < 4; c++) acc[mi][ni][c] = 0.f;

    // cp.async stage: A 128x16 (512 16B-chunks), B 16x128 (512 chunks); 4 each per thread
    auto stage = [&](int s, int k0) {
#pragma unroll
        for (int i = 0; i < 4; i++) {
            int c  = i * 128 + tid;
            int ar = c >> 2, ac = (c & 3) * 4;
            cp16(as_base + (s * ASTG + ar * LDA + ac) * 4,
                 Ab + (size_t)ar * K + k0 + ac);
            int br = c >> 5, bc = (c & 31) * 4;
            cp16(bs_base + (s * BSTG + br * LDB + bc) * 4,
                 Bb + (size_t)(k0 + br) * N + bc);
        }
        asm volatile("cp.async.commit_group;\n" ::);
    };

    const int nk = K / GBK;
    stage(0, 0);

    for (int kt = 0; kt < nk; kt++) {
        const int s = kt & 1;
        if (kt + 1 < nk) {
            stage(s ^ 1, (kt + 1) * GBK);
            asm volatile("cp.async.wait_group 1;\n" ::);
        } else {
            asm volatile("cp.async.wait_group 0;\n" ::);
        }
        __syncthreads();

        const uint32_t* Asb = &As[s][0];
        const uint32_t* Bsb = &Bs[s][0];
#pragma unroll
        for (int kk = 0; kk < 2; kk++) {
            uint32_t af[4][4];
#pragma unroll
            for (int mi = 0; mi < 4; mi++) {
                const int mr = warp_m + mi * 16;
                af[mi][0] = Asb[(mr + g)     * LDA + kk * 8 + t];
                af[mi][1] = Asb[(mr + g + 8) * LDA + kk * 8 + t];
                af[mi][2] = Asb[(mr + g)     * LDA + kk * 8 + t + 4];
                af[mi][3] = Asb[(mr + g + 8) * LDA + kk * 8 + t + 4];
            }
#pragma unroll
            for (int ni = 0; ni < 8; ni++) {
                uint32_t bf[2];
                bf[0] = Bsb[(kk * 8 + t)     * LDB + warp_n + ni * 8 + g];
                bf[1] = Bsb[(kk * 8 + t + 4) * LDB + warp_n + ni * 8 + g];
#pragma unroll
                for (int mi = 0; mi < 4; mi++)
                    mma_tf32(acc[mi][ni], af[mi], bf);
            }
        }
        __syncthreads();
    }

    // ---- epilogue: c0=(g,2t) c1=(g,2t+1) c2=(g+8,2t) c3=(g+8,2t+1) ----
#pragma unroll
    for (int mi = 0; mi < 4; mi++) {
        const int r0 = bm + warp_m + mi * 16 + g;
        float* cr0 = C + (size_t)r0 * N + bn;
        float* cr1 = cr0 + (size_t)8 * N;
#pragma unroll
        for (int ni = 0; ni < 8; ni++) {
            const int cc = warp_n + ni * 8 + 2 * t;
            float bx = 0.f, by = 0.f;
            if (bias) {
                bx = __ldg(&bias[bn + cc]);
                by = __ldg(&bias[bn + cc + 1]);
            }
            float2 v0, v1;
            v0.x = acc[mi][ni][0] + bx; v0.y = acc[mi][ni][1] + by;
            v1.x = acc[mi][ni][2] + bx; v1.y = acc[mi][ni][3] + by;
            *(float2*)(cr0 + cc) = v0;
            *(float2*)(cr1 + cc) = v1;
        }
    }
}

// ---------------------------------------------------------------------------
// Flash attention, tf32 mma, bias via smem, softmax in exp2 domain.
// grid = (SEQ/128, B*H); block = 256 (8 warps), 16 query rows per warp.
// smem: Ks 64x68 | Vs 64x68 | Ps 8*(16x68) | Bt 63x64  = 85760 B
// ---------------------------------------------------------------------------
#define QTILE 128
#define KTILE 64
#define LDK   68
#define BT_ELEMS (63 * 64)
#define FA_SMEM ((2 * 64 * LDK + 8 * 16 * LDK + BT_ELEMS) * 4)

__global__ __launch_bounds__(256)
void flash_attn_tc(const float* __restrict__ qkv,
                   const float* __restrict__ bias_table,
                   float* __restrict__ ctx)
{
    extern __shared__ float sm[];
    float* Ks = sm;                    // 64 x 68 (tf32 bits)
    float* Vs = Ks + 64 * LDK;         // 64 x 68 (tf32 bits)
    float* Ps = Vs + 64 * LDK;         // 8 warps x 16 x 68
    float* Bt = Ps + 8 * 16 * LDK;     // 63 x 64 (per-head bias * log2e)

    const int bh = blockIdx.y;
    const int b  = bh / HEADS;
    const int h  = bh % HEADS;
    const int r0 = blockIdx.x * QTILE;

    const int tid  = threadIdx.x;
    const int wid  = tid >> 5;
    const int lane = tid & 31;
    const int g    = lane >> 2;     // 0..7
    const int t    = lane & 3;      // 0..3

    float* Pw = Ps + wid * 16 * LDK;

    // ---- stage per-head bias slice into smem, scaled by log2(e) ----
    for (int v = tid; v < 63 * 63; v += 256) {
        int r = v / 63, c = v - r * 63;
        Bt[r * 64 + c] = __ldg(&bias_table[v * HEADS + h]) * LOG2E;
    }

    // ---- load Q A-fragments (16 rows per warp), scale 0.125*log2e ----
    const float qscale = 0.125f * LOG2E;
    uint32_t qa[8][4];
    {
        const int qr0 = b * SEQ + r0 + wid * 16;
        const float* qb = qkv + (size_t)qr0 * QKVCOLS + h * HDIM;
#pragma unroll
        for (int kk = 0; kk < 8; kk++) {
            qa[kk][0] = f2tf32(qscale * __ldg(qb + (size_t)g       * QKVCOLS + kk * 8 + t));
            qa[kk][1] = f2tf32(qscale * __ldg(qb + (size_t)(g + 8) * QKVCOLS + kk * 8 + t));
            qa[kk][2] = f2tf32(qscale * __ldg(qb + (size_t)g       * QKVCOLS + kk * 8 + t + 4));
            qa[kk][3] = f2tf32(qscale * __ldg(qb + (size_t)(g + 8) * QKVCOLS + kk * 8 + t + 4));
        }
    }

    float o[8][4];
#pragma unroll
    for (int nt = 0; nt < 8; nt++)
#pragma unroll
        for (int c = 0; c < 4; c++) o[nt][c] = 0.f;

    float m0 = -CUDART_INF_F, m1 = -CUDART_INF_F;
    float l0 = 0.f, l1 = 0.f;

    // per-thread bias row constants: ci = (i>>5)*64 + (i&31) + 31*65
    const int i0 = r0 + wid * 16 + g;
    const int i1 = i0 + 8;
    const int ci0 = (i0 >> 5) * 64 + (i0 & 31) + 2015;
    const int ci1 = (i1 >> 5) * 64 + (i1 & 31) + 2015;

    const int lr = tid >> 2;        // 0..63 (K/V tile loader row)
    const int lc = (tid & 3) * 4;   // base float4 col

    for (int tk = 0; tk < SEQ / KTILE; tk++) {
        __syncthreads();
        // ---- stage K,V tile into smem (tf32-rounded) ----
        {
            const float* kb = qkv + (size_t)(b * SEQ + tk * KTILE + lr) * QKVCOLS + DIM + h * HDIM;
            const float* vb = kb + DIM;
#pragma unroll
            for (int k = 0; k < 4; k++) {
                int c = lc + 16 * k;
                float4 kv = *(const float4*)(kb + c);
                float4 vv = *(const float4*)(vb + c);
                uint4 ko, vo;
                ko.x = f2tf32(kv.x); ko.y = f2tf32(kv.y); ko.z = f2tf32(kv.z); ko.w = f2tf32(kv.w);
                vo.x = f2tf32(vv.x); vo.y = f2tf32(vv.y); vo.z = f2tf32(vv.z); vo.w = f2tf32(vv.w);
                *(uint4*)&Ks[lr * LDK + c] = ko;
                *(uint4*)&Vs[lr * LDK + c] = vo;
            }
        }
        __syncthreads();

        // ---- S = Q K^T (scores in log2 domain) ----
        float s[8][4];
#pragma unroll
        for (int nt = 0; nt < 8; nt++)
#pragma unroll
            for (int c = 0; c < 4; c++) s[nt][c] = 0.f;

        const uint32_t* Kb = (const uint32_t*)Ks;
#pragma unroll
        for (int kk = 0; kk < 8; kk++) {
#pragma unroll
            for (int nt = 0; nt < 8; nt++) {
                uint32_t bfr[2];
                bfr[0] = Kb[(nt * 8 + g) * LDK + kk * 8 + t];
                bfr[1] = Kb[(nt * 8 + g) * LDK + kk * 8 + t + 4];
                mma_tf32(s[nt], qa[kk], bfr);
            }
        }

        // ---- bias (smem) + running softmax (exp2 domain) ----
        float mt0 = -CUDART_INF_F, mt1 = -CUDART_INF_F;
        const int jbase = tk * KTILE + 2 * t;
#pragma unroll
        for (int nt = 0; nt < 8; nt++) {
            int j0 = jbase + nt * 8;
            int cj = j0 + (j0 & ~31);       // (j>>5)*64 + (j&31)
            s[nt][0] += Bt[ci0 - cj];
            s[nt][1] += Bt[ci0 - cj - 1];
            s[nt][2] += Bt[ci1 - cj];
            s[nt][3] += Bt[ci1 - cj - 1];
            mt0 = fmaxf(mt0, fmaxf(s[nt][0], s[nt][1]));
            mt1 = fmaxf(mt1, fmaxf(s[nt][2], s[nt][3]));
        }
        mt0 = fmaxf(mt0, __shfl_xor_sync(0xffffffffu, mt0, 1));
        mt0 = fmaxf(mt0, __shfl_xor_sync(0xffffffffu, mt0, 2));
        mt1 = fmaxf(mt1, __shfl_xor_sync(0xffffffffu, mt1, 1));
        mt1 = fmaxf(mt1, __shfl_xor_sync(0xffffffffu, mt1, 2));

        float mn0 = fmaxf(m0, mt0);
        float mn1 = fmaxf(m1, mt1);
        float a0 = exp2f(m0 - mn0);
        float a1 = exp2f(m1 - mn1);
        m0 = mn0; m1 = mn1;

        float ls0 = 0.f, ls1 = 0.f;
#pragma unroll
        for (int nt = 0; nt < 8; nt++) {
            float p00 = exp2f(s[nt][0] - mn0);
            float p01 = exp2f(s[nt][1] - mn0);
            float p10 = exp2f(s[nt][2] - mn1);
            float p11 = exp2f(s[nt][3] - mn1);
            ls0 += p00 + p01;
            ls1 += p10 + p11;
            float2 w0, w1;
            w0.x = __uint_as_float(f2tf32(p00));
            w0.y = __uint_as_float(f2tf32(p01));
            w1.x = __uint_as_float(f2tf32(p10));
            w1.y = __uint_as_float(f2tf32(p11));
            *(float2*)&Pw[g * LDK + nt * 8 + 2 * t]       = w0;
            *(float2*)&Pw[(g + 8) * LDK + nt * 8 + 2 * t] = w1;
        }
        ls0 += __shfl_xor_sync(0xffffffffu, ls0, 1);
        ls0 += __shfl_xor_sync(0xffffffffu, ls0, 2);
        ls1 += __shfl_xor_sync(0xffffffffu, ls1, 1);
        ls1 += __shfl_xor_sync(0xffffffffu, ls1, 2);
        l0 = l0 * a0 + ls0;
        l1 = l1 * a1 + ls1;

#pragma unroll
        for (int nt = 0; nt < 8; nt++) {
            o[nt][0] *= a0; o[nt][1] *= a0;
            o[nt][2] *= a1; o[nt][3] *= a1;
        }
        __syncwarp();

        // ---- O += P V ----
        const uint32_t* Pb = (const uint32_t*)Pw;
        const uint32_t* Vb = (const uint32_t*)Vs;
#pragma unroll
        for (int kk = 0; kk < 8; kk++) {
            uint32_t afr[4];
            afr[0] = Pb[g * LDK + kk * 8 + t];
            afr[1] = Pb[(g + 8) * LDK + kk * 8 + t];
            afr[2] = Pb[g * LDK + kk * 8 + t + 4];
            afr[3] = Pb[(g + 8) * LDK + kk * 8 + t + 4];
#pragma unroll
            for (int nt = 0; nt < 8; nt++) {
                uint32_t bfr[2];
                bfr[0] = Vb[(kk * 8 + t) * LDK + nt * 8 + g];
                bfr[1] = Vb[(kk * 8 + t + 4) * LDK + nt * 8 + g];
                mma_tf32(o[nt], afr, bfr);
            }
        }
        __syncwarp();
    }

    // ---- normalize and write ctx ----
    float inv0 = 1.f / l0;
    float inv1 = 1.f / l1;
    const int orow0 = b * SEQ + r0 + wid * 16 + g;
    float* ob0 = ctx + (size_t)orow0 * DIM + h * HDIM + 2 * t;
    float* ob1 = ctx + (size_t)(orow0 + 8) * DIM + h * HDIM + 2 * t;
#pragma unroll
    for (int nt = 0; nt < 8; nt++) {
        float2 v0, v1;
        v0.x = o[nt][0] * inv0; v0.y = o[nt][1] * inv0;
        v1.x = o[nt][2] * inv1; v1.y = o[nt][3] * inv1;
        *(float2*)(ob0 + nt * 8) = v0;
        *(float2*)(ob1 + nt * 8) = v1;
    }
}

// ---------------------------------------------------------------------------
extern "C" void kernel_launch(void* const* d_in, const int* in_sizes, int n_in,
                              void* d_out, int out_size)
{
    const float* x          = (const float*)d_in[0];
    const float* qkv_w      = (const float*)d_in[1];
    const float* proj_w     = (const float*)d_in[2];
    const float* proj_b     = (const float*)d_in[3];
    const float* bias_table = (const float*)d_in[4];
    // d_in[5] = rel_index (int32) — computed analytically, unused
    float* out = (float*)d_out;

    float *qkv_s, *ctx_s;
    cudaGetSymbolAddress((void**)&qkv_s, g_qkv);
    cudaGetSymbolAddress((void**)&ctx_s, g_ctx);

    // 1) qkv = x @ qkv_w  (tf32 tensor cores, cp.async)
    {
        dim3 grid(QKVCOLS / 128, ROWS / 128);
        tgemm_db<<<grid, 128>>>(x, qkv_w, nullptr, qkv_s, ROWS, QKVCOLS, DIM);
    }

    // 2) flash attention (tf32 tensor cores, smem bias)
    {
        cudaFuncSetAttribute(flash_attn_tc, cudaFuncAttributeMaxDynamicSharedMemorySize, FA_SMEM);
        dim3 grid(SEQ / QTILE, BATCH * HEADS);
        flash_attn_tc<<<grid, 256, FA_SMEM>>>(qkv_s, bias_table, ctx_s);
    }

    // 3) out = ctx @ proj_w + proj_b  (tf32 tensor cores, cp.async)
    {
        dim3 grid(DIM / 128, ROWS / 128);
        tgemm_db<<<grid, 128>>>(ctx_s, proj_w, proj_b, out, ROWS, DIM, DIM);
    }
}

// round 10
// speedup vs baseline: 7.1018x; 1.2722x over previous
#include <cuda_runtime.h>
#include <cuda_fp16.h>
#include <cuda_bf16.h>
#include <math_constants.h>
#include <cstdint>

// ---------------------------------------------------------------------------
// RelativeAttention: B=8, N=1024, C=768, H=12, hd=64, MAX_DIST=32
//   qkv = x @ qkv_w        (tf32 mma GEMM, cp.async, RNA-emulated rounding)
//   attention              (fp16 m16n8k16 mma flash attention, smem bias)
//   out = ctx @ proj_w + b (tf32 mma GEMM)
// rel_index analytic: idx = ((i>>5)-(j>>5)+31)*63 + ((i&31)-(j&31)+31)
// ---------------------------------------------------------------------------

#define BATCH   8
#define SEQ     1024
#define DIM     768
#define HEADS   12
#define HDIM    64
#define ROWS    (BATCH * SEQ)       // 8192
#define QKVCOLS (3 * DIM)           // 2304
#define LOG2E   1.4426950408889634f

__device__ float g_qkv[ROWS * QKVCOLS];   // ~75.5 MB
__device__ float g_ctx[ROWS * DIM];       // ~25.2 MB

// ---------------------------------------------------------------------------
__device__ __forceinline__ uint32_t f2tf32(float x) {
    uint32_t r;
    asm("cvt.rna.tf32.f32 %0, %1;" : "=r"(r) : "f"(x));
    return r;
}

__device__ __forceinline__ uint32_t h2u(__half2 h) {
    uint32_t u;
    memcpy(&u, &h, 4);
    return u;
}

__device__ __forceinline__ void mma_tf32(float c[4], const uint32_t a[4], const uint32_t b[2]) {
    asm volatile(
        "mma.sync.aligned.m16n8k8.row.col.f32.tf32.tf32.f32 "
        "{%0,%1,%2,%3}, {%4,%5,%6,%7}, {%8,%9}, {%0,%1,%2,%3};\n"
        : "+f"(c[0]), "+f"(c[1]), "+f"(c[2]), "+f"(c[3])
        : "r"(a[0]), "r"(a[1]), "r"(a[2]), "r"(a[3]), "r"(b[0]), "r"(b[1]));
}

__device__ __forceinline__ void mma_f16(float c[4], const uint32_t a[4], const uint32_t b[2]) {
    asm volatile(
        "mma.sync.aligned.m16n8k16.row.col.f32.f16.f16.f32 "
        "{%0,%1,%2,%3}, {%4,%5,%6,%7}, {%8,%9}, {%0,%1,%2,%3};\n"
        : "+f"(c[0]), "+f"(c[1]), "+f"(c[2]), "+f"(c[3])
        : "r"(a[0]), "r"(a[1]), "r"(a[2]), "r"(a[3]), "r"(b[0]), "r"(b[1]));
}

__device__ __forceinline__ void cp16(uint32_t smem_addr, const void* gptr) {
    asm volatile("cp.async.ca.shared.global [%0], [%1], 16;\n"
                 :: "r"(smem_addr), "l"(gptr));
}

// half-ULP pre-add so HW tf32 truncation behaves like round-to-nearest
#define RNA13(u) ((u) + 0x1000u)

// ---------------------------------------------------------------------------
// tf32 tensor-core GEMM, cp.async double-buffered.
// Block 128x128, BK=16, 128 threads (4 warps, 2x2), warp tile 64x64.
// ---------------------------------------------------------------------------
#define GBK  16
#define LDA  20
#define LDB  136
#define ASTG (128 * LDA)
#define BSTG (GBK * LDB)

__global__ __launch_bounds__(128, 2)
void tgemm_db(const float* __restrict__ A, const float* __restrict__ B,
              const float* __restrict__ bias, float* __restrict__ C,
              int M, int N, int K)
{
    __shared__ __align__(16) uint32_t As[2][ASTG];   // [m][k]
    __shared__ __align__(16) uint32_t Bs[2][BSTG];   // [k][n]

    const int tid  = threadIdx.x;
    const int wid  = tid >> 5;
    const int lane = tid & 31;
    const int g    = lane >> 2;
    const int t    = lane & 3;

    const int bm = blockIdx.y * 128;
    const int bn = blockIdx.x * 128;

    const int warp_m = (wid & 1) * 64;
    const int warp_n = (wid >> 1) * 64;

    const float* Ab = A + (size_t)bm * K;
    const float* Bb = B + bn;

    const uint32_t as_base = (uint32_t)__cvta_generic_to_shared(&As[0][0]);
    const uint32_t bs_base = (uint32_t)__cvta_generic_to_shared(&Bs[0][0]);

    float acc[4][8][4];
#pragma unroll
    for (int mi = 0; mi < 4; mi++)
#pragma unroll
        for (int ni = 0; ni < 8; ni++)
#pragma unroll
            for (int c = 0; c < 4; c++) acc[mi][ni][c] = 0.f;

    auto stage = [&](int s, int k0) {
#pragma unroll
        for (int i = 0; i < 4; i++) {
            int c  = i * 128 + tid;
            int ar = c >> 2, ac = (c & 3) * 4;
            cp16(as_base + (s * ASTG + ar * LDA + ac) * 4,
                 Ab + (size_t)ar * K + k0 + ac);
            int br = c >> 5, bc = (c & 31) * 4;
            cp16(bs_base + (s * BSTG + br * LDB + bc) * 4,
                 Bb + (size_t)(k0 + br) * N + bc);
        }
        asm volatile("cp.async.commit_group;\n" ::);
    };

    const int nk = K / GBK;
    stage(0, 0);

    for (int kt = 0; kt < nk; kt++) {
        const int s = kt & 1;
        if (kt + 1 < nk) {
            stage(s ^ 1, (kt + 1) * GBK);
            asm volatile("cp.async.wait_group 1;\n" ::);
        } else {
            asm volatile("cp.async.wait_group 0;\n" ::);
        }
        __syncthreads();

        const uint32_t* Asb = &As[s][0];
        const uint32_t* Bsb = &Bs[s][0];
#pragma unroll
        for (int kk = 0; kk < 2; kk++) {
            uint32_t af[4][4];
#pragma unroll
            for (int mi = 0; mi < 4; mi++) {
                const int mr = warp_m + mi * 16;
                af[mi][0] = RNA13(Asb[(mr + g)     * LDA + kk * 8 + t]);
                af[mi][1] = RNA13(Asb[(mr + g + 8) * LDA + kk * 8 + t]);
                af[mi][2] = RNA13(Asb[(mr + g)     * LDA + kk * 8 + t + 4]);
                af[mi][3] = RNA13(Asb[(mr + g + 8) * LDA + kk * 8 + t + 4]);
            }
#pragma unroll
            for (int ni = 0; ni < 8; ni++) {
                uint32_t bf[2];
                bf[0] = RNA13(Bsb[(kk * 8 + t)     * LDB + warp_n + ni * 8 + g]);
                bf[1] = RNA13(Bsb[(kk * 8 + t + 4) * LDB + warp_n + ni * 8 + g]);
#pragma unroll
                for (int mi = 0; mi < 4; mi++)
                    mma_tf32(acc[mi][ni], af[mi], bf);
            }
        }
        __syncthreads();
    }

#pragma unroll
    for (int mi = 0; mi < 4; mi++) {
        const int r0 = bm + warp_m + mi * 16 + g;
        float* cr0 = C + (size_t)r0 * N + bn;
        float* cr1 = cr0 + (size_t)8 * N;
#pragma unroll
        for (int ni = 0; ni < 8; ni++) {
            const int cc = warp_n + ni * 8 + 2 * t;
            float bx = 0.f, by = 0.f;
            if (bias) {
                bx = __ldg(&bias[bn + cc]);
                by = __ldg(&bias[bn + cc + 1]);
            }
            float2 v0, v1;
            v0.x = acc[mi][ni][0] + bx; v0.y = acc[mi][ni][1] + by;
            v1.x = acc[mi][ni][2] + bx; v1.y = acc[mi][ni][3] + by;
            *(float2*)(cr0 + cc) = v0;
            *(float2*)(cr1 + cc) = v1;
        }
    }
}

// ---------------------------------------------------------------------------
// Flash attention, fp16 m16n8k16 mma, bias via smem, softmax exp2 domain.
// grid = (SEQ/128, B*H); block = 256 (8 warps), 16 query rows per warp.
// smem (halves, LDH=72 pad): Ks[64][72] | Vt[64][72] (V transposed) |
//                            Pw 8x[16][72] | Bt[63][64] f32  = 53 KB
// ---------------------------------------------------------------------------
#define QTILE 128
#define KTILE 64
#define LDH   72
#define BT_ELEMS (63 * 64)
#define FA_SMEM ((64 * LDH + 64 * LDH + 8 * 16 * LDH) * 2 + BT_ELEMS * 4)

__global__ __launch_bounds__(256)
void flash_attn_f16(const float* __restrict__ qkv,
                    const float* __restrict__ bias_table,
                    float* __restrict__ ctx)
{
    extern __shared__ char smraw[];
    __half* Ks = (__half*)smraw;            // [key][dim]
    __half* Vt = Ks + 64 * LDH;             // [dim][key] (transposed)
    __half* Ps = Vt + 64 * LDH;             // 8 warps x [row][key]
    float*  Bt = (float*)(Ps + 8 * 16 * LDH);  // [63][64] bias * log2e

    const int bh = blockIdx.y;
    const int b  = bh / HEADS;
    const int h  = bh % HEADS;
    const int r0 = blockIdx.x * QTILE;

    const int tid  = threadIdx.x;
    const int wid  = tid >> 5;
    const int lane = tid & 31;
    const int g    = lane >> 2;
    const int t    = lane & 3;

    __half* Pw = Ps + wid * 16 * LDH;
    const uint32_t* Kw = (const uint32_t*)Ks;   // half2 view
    const uint32_t* Vw = (const uint32_t*)Vt;
    const uint32_t* Pb = (const uint32_t*)Pw;
    const int LDH2 = LDH / 2;                   // 36 half2 per row

    // ---- stage per-head bias slice into smem, scaled by log2(e) ----
    for (int v = tid; v < 63 * 63; v += 256) {
        int r = v / 63, c = v - r * 63;
        Bt[r * 64 + c] = __ldg(&bias_table[v * HEADS + h]) * LOG2E;
    }

    // ---- Q A-fragments fp16: qa[kk][0..3], kk = 4 k16-steps over 64 dims ----
    const float qscale = 0.125f * LOG2E;
    uint32_t qa[4][4];
    {
        const int qr0 = b * SEQ + r0 + wid * 16;
        const float* qb = qkv + (size_t)qr0 * QKVCOLS + h * HDIM;
#pragma unroll
        for (int kk = 0; kk < 4; kk++) {
            int c0 = kk * 16 + 2 * t;
#pragma unroll
            for (int half8 = 0; half8 < 2; half8++) {
                int c = c0 + half8 * 8;
                float x0 = qscale * __ldg(qb + (size_t)g       * QKVCOLS + c);
                float x1 = qscale * __ldg(qb + (size_t)g       * QKVCOLS + c + 1);
                float y0 = qscale * __ldg(qb + (size_t)(g + 8) * QKVCOLS + c);
                float y1 = qscale * __ldg(qb + (size_t)(g + 8) * QKVCOLS + c + 1);
                qa[kk][half8 * 2 + 0] = h2u(__floats2half2_rn(x0, x1));
                qa[kk][half8 * 2 + 1] = h2u(__floats2half2_rn(y0, y1));
            }
        }
    }

    float o[8][4];
#pragma unroll
    for (int nt = 0; nt < 8; nt++)
#pragma unroll
        for (int c = 0; c < 4; c++) o[nt][c] = 0.f;

    float m0 = -CUDART_INF_F, m1 = -CUDART_INF_F;
    float l0 = 0.f, l1 = 0.f;

    const int i0 = r0 + wid * 16 + g;
    const int i1 = i0 + 8;
    const int ci0 = (i0 >> 5) * 64 + (i0 & 31) + 2015;
    const int ci1 = (i1 >> 5) * 64 + (i1 & 31) + 2015;

    const int lr = tid >> 2;        // 0..63 loader row (key)
    const int lc = (tid & 3) * 4;   // loader dim base

    for (int tk = 0; tk < SEQ / KTILE; tk++) {
        __syncthreads();
        // ---- stage K [key][dim] and V transposed [dim][key], fp16 ----
        {
            const float* kb = qkv + (size_t)(b * SEQ + tk * KTILE + lr) * QKVCOLS + DIM + h * HDIM;
            const float* vb = kb + DIM;
#pragma unroll
            for (int k = 0; k < 4; k++) {
                int c = lc + 16 * k;
                float4 kv = *(const float4*)(kb + c);
                float4 vv = *(const float4*)(vb + c);
                __half2* kd = (__half2*)&Ks[lr * LDH + c];
                kd[0] = __floats2half2_rn(kv.x, kv.y);
                kd[1] = __floats2half2_rn(kv.z, kv.w);
                Vt[(c + 0) * LDH + lr] = __float2half_rn(vv.x);
                Vt[(c + 1) * LDH + lr] = __float2half_rn(vv.y);
                Vt[(c + 2) * LDH + lr] = __float2half_rn(vv.z);
                Vt[(c + 3) * LDH + lr] = __float2half_rn(vv.w);
            }
        }
        __syncthreads();

        // ---- S = Q K^T : 4 k16-steps x 8 n-tiles ----
        float s[8][4];
#pragma unroll
        for (int nt = 0; nt < 8; nt++)
#pragma unroll
            for (int c = 0; c < 4; c++) s[nt][c] = 0.f;

#pragma unroll
        for (int kk = 0; kk < 4; kk++) {
#pragma unroll
            for (int nt = 0; nt < 8; nt++) {
                uint32_t bf[2];
                const int key = nt * 8 + g;
                bf[0] = Kw[key * LDH2 + kk * 8 + t];       // dims kk*16+2t,+1
                bf[1] = Kw[key * LDH2 + kk * 8 + t + 4];   // dims kk*16+2t+8,+9
                mma_f16(s[nt], qa[kk], bf);
            }
        }

        // ---- bias (smem) + running softmax (exp2 domain) ----
        float mt0 = -CUDART_INF_F, mt1 = -CUDART_INF_F;
        const int jbase = tk * KTILE + 2 * t;
#pragma unroll
        for (int nt = 0; nt < 8; nt++) {
            int j0 = jbase + nt * 8;
            int cj = j0 + (j0 & ~31);
            s[nt][0] += Bt[ci0 - cj];
            s[nt][1] += Bt[ci0 - cj - 1];
            s[nt][2] += Bt[ci1 - cj];
            s[nt][3] += Bt[ci1 - cj - 1];
            mt0 = fmaxf(mt0, fmaxf(s[nt][0], s[nt][1]));
            mt1 = fmaxf(mt1, fmaxf(s[nt][2], s[nt][3]));
        }
        mt0 = fmaxf(mt0, __shfl_xor_sync(0xffffffffu, mt0, 1));
        mt0 = fmaxf(mt0, __shfl_xor_sync(0xffffffffu, mt0, 2));
        mt1 = fmaxf(mt1, __shfl_xor_sync(0xffffffffu, mt1, 1));
        mt1 = fmaxf(mt1, __shfl_xor_sync(0xffffffffu, mt1, 2));

        float mn0 = fmaxf(m0, mt0);
        float mn1 = fmaxf(m1, mt1);
        float a0 = exp2f(m0 - mn0);
        float a1 = exp2f(m1 - mn1);
        m0 = mn0; m1 = mn1;

        float ls0 = 0.f, ls1 = 0.f;
#pragma unroll
        for (int nt = 0; nt < 8; nt++) {
            float p00 = exp2f(s[nt][0] - mn0);
            float p01 = exp2f(s[nt][1] - mn0);
            float p10 = exp2f(s[nt][2] - mn1);
            float p11 = exp2f(s[nt][3] - mn1);
            ls0 += p00 + p01;
            ls1 += p10 + p11;
            *(__half2*)&Pw[g * LDH + nt * 8 + 2 * t]       = __floats2half2_rn(p00, p01);
            *(__half2*)&Pw[(g + 8) * LDH + nt * 8 + 2 * t] = __floats2half2_rn(p10, p11);
        }
        ls0 += __shfl_xor_sync(0xffffffffu, ls0, 1);
        ls0 += __shfl_xor_sync(0xffffffffu, ls0, 2);
        ls1 += __shfl_xor_sync(0xffffffffu, ls1, 1);
        ls1 += __shfl_xor_sync(0xffffffffu, ls1, 2);
        l0 = l0 * a0 + ls0;
        l1 = l1 * a1 + ls1;

#pragma unroll
        for (int nt = 0; nt < 8; nt++) {
            o[nt][0] *= a0; o[nt][1] *= a0;
            o[nt][2] *= a1; o[nt][3] *= a1;
        }
        __syncwarp();

        // ---- O += P V : 4 k16-steps (keys) x 8 n-tiles (dims) ----
#pragma unroll
        for (int kk = 0; kk < 4; kk++) {
            uint32_t af[4];
            af[0] = Pb[g       * LDH2 + kk * 8 + t];       // keys kk*16+2t,+1
            af[1] = Pb[(g + 8) * LDH2 + kk * 8 + t];
            af[2] = Pb[g       * LDH2 + kk * 8 + t + 4];   // keys kk*16+2t+8,+9
            af[3] = Pb[(g + 8) * LDH2 + kk * 8 + t + 4];
#pragma unroll
            for (int nt = 0; nt < 8; nt++) {
                uint32_t bf[2];
                const int dim = nt * 8 + g;
                bf[0] = Vw[dim * LDH2 + kk * 8 + t];
                bf[1] = Vw[dim * LDH2 + kk * 8 + t + 4];
                mma_f16(o[nt], af, bf);
            }
        }
        __syncwarp();
    }

    // ---- normalize and write ctx ----
    float inv0 = 1.f / l0;
    float inv1 = 1.f / l1;
    const int orow0 = b * SEQ + r0 + wid * 16 + g;
    float* ob0 = ctx + (size_t)orow0 * DIM + h * HDIM + 2 * t;
    float* ob1 = ctx + (size_t)(orow0 + 8) * DIM + h * HDIM + 2 * t;
#pragma unroll
    for (int nt = 0; nt < 8; nt++) {
        float2 v0, v1;
        v0.x = o[nt][0] * inv0; v0.y = o[nt][1] * inv0;
        v1.x = o[nt][2] * inv1; v1.y = o[nt][3] * inv1;
        *(float2*)(ob0 + nt * 8) = v0;
        *(float2*)(ob1 + nt * 8) = v1;
    }
}

// ---------------------------------------------------------------------------
extern "C" void kernel_launch(void* const* d_in, const int* in_sizes, int n_in,
                              void* d_out, int out_size)
{
    const float* x          = (const float*)d_in[0];
    const float* qkv_w      = (const float*)d_in[1];
    const float* proj_w     = (const float*)d_in[2];
    const float* proj_b     = (const float*)d_in[3];
    const float* bias_table = (const float*)d_in[4];
    // d_in[5] = rel_index (int32) — computed analytically, unused
    float* out = (float*)d_out;

    float *qkv_s, *ctx_s;
    cudaGetSymbolAddress((void**)&qkv_s, g_qkv);
    cudaGetSymbolAddress((void**)&ctx_s, g_ctx);

    // 1) qkv = x @ qkv_w
    {
        dim3 grid(QKVCOLS / 128, ROWS / 128);
        tgemm_db<<<grid, 128>>>(x, qkv_w, nullptr, qkv_s, ROWS, QKVCOLS, DIM);
    }

    // 2) flash attention (fp16 tensor cores, smem bias)
    {
        cudaFuncSetAttribute(flash_attn_f16, cudaFuncAttributeMaxDynamicSharedMemorySize, FA_SMEM);
        dim3 grid(SEQ / QTILE, BATCH * HEADS);
        flash_attn_f16<<<grid, 256, FA_SMEM>>>(qkv_s, bias_table, ctx_s);
    }

    // 3) out = ctx @ proj_w + proj_b
    {
        dim3 grid(DIM / 128, ROWS / 128);
        tgemm_db<<<grid, 128>>>(ctx_s, proj_w, proj_b, out, ROWS, DIM, DIM);
    }
}

// round 11
// speedup vs baseline: 9.2649x; 1.3046x over previous
#include <cuda_runtime.h>
#include <cuda_fp16.h>
#include <cuda_bf16.h>
#include <math_constants.h>
#include <cstdint>
#include <cstring>

// ---------------------------------------------------------------------------
// RelativeAttention: B=8, N=1024, C=768, H=12, hd=64, MAX_DIST=32
// Full fp16 pipeline (fp32 accumulate everywhere):
//   prep:  x -> fp16; qkv_w, proj_w -> transposed fp16 [N][K]
//   qkv  = x @ qkv_w          (fp16 m16n8k16 GEMM, cp.async, fp16 out)
//   attn                      (fp16 m16n8k16 flash attention, smem bias)
//   out  = ctx @ proj_w + b   (fp16 m16n8k16 GEMM, fp32 out)
// rel_index analytic: idx = ((i>>5)-(j>>5)+31)*63 + ((i&31)-(j&31)+31)
// ---------------------------------------------------------------------------

#define BATCH   8
#define SEQ     1024
#define DIM     768
#define HEADS   12
#define HDIM    64
#define ROWS    (BATCH * SEQ)       // 8192
#define QKVCOLS (3 * DIM)           // 2304
#define LOG2E   1.4426950408889634f

// scratch (device globals: allocation-free)
__device__ __half g_hx[ROWS * DIM];          // 12.6 MB
__device__ __half g_w1t[QKVCOLS * DIM];      // 3.5 MB  (qkv_w^T)
__device__ __half g_w2t[DIM * DIM];          // 1.2 MB  (proj_w^T)
__device__ __half g_qkvh[ROWS * QKVCOLS];    // 37.7 MB
__device__ __half g_ctxh[ROWS * DIM];        // 12.6 MB

// ---------------------------------------------------------------------------
__device__ __forceinline__ uint32_t h2u(__half2 h) {
    uint32_t u;
    memcpy(&u, &h, 4);
    return u;
}

__device__ __forceinline__ void mma_f16(float c[4], const uint32_t a[4], const uint32_t b[2]) {
    asm volatile(
        "mma.sync.aligned.m16n8k16.row.col.f32.f16.f16.f32 "
        "{%0,%1,%2,%3}, {%4,%5,%6,%7}, {%8,%9}, {%0,%1,%2,%3};\n"
        : "+f"(c[0]), "+f"(c[1]), "+f"(c[2]), "+f"(c[3])
        : "r"(a[0]), "r"(a[1]), "r"(a[2]), "r"(a[3]), "r"(b[0]), "r"(b[1]));
}

__device__ __forceinline__ void cp16(uint32_t smem_addr, const void* gptr) {
    asm volatile("cp.async.ca.shared.global [%0], [%1], 16;\n"
                 :: "r"(smem_addr), "l"(gptr));
}

// ---------------------------------------------------------------------------
// prep kernels
// ---------------------------------------------------------------------------
__global__ void cvt_fp16(const float* __restrict__ in, __half* __restrict__ out, int n4)
{
    int i = blockIdx.x * blockDim.x + threadIdx.x;
    if (i < n4) {
        float4 v = *(const float4*)(in + i * 4);
        __half2* o = (__half2*)(out + i * 4);
        o[0] = __floats2half2_rn(v.x, v.y);
        o[1] = __floats2half2_rn(v.z, v.w);
    }
}

// in [R][C] fp32 -> out [C][R] fp16; R,C multiples of 32; block (32,8)
__global__ void cvt_t(const float* __restrict__ in, __half* __restrict__ out, int R, int C)
{
    __shared__ __half ts[32][33];
    const int tx = threadIdx.x, ty = threadIdx.y;
    const int c0 = blockIdx.x * 32, r0 = blockIdx.y * 32;
#pragma unroll
    for (int j = 0; j < 4; j++) {
        int r = r0 + ty + j * 8;
        ts[ty + j * 8][tx] = __float2half_rn(in[(size_t)r * C + c0 + tx]);
    }
    __syncthreads();
#pragma unroll
    for (int j = 0; j < 4; j++) {
        out[(size_t)(c0 + ty + j * 8) * R + r0 + tx] = ts[tx][ty + j * 8];
    }
}

// ---------------------------------------------------------------------------
// fp16 GEMM: C[M,N] = A[M,K] @ Bt[N,K]^T (+ bias[N])
// A, Bt fp16 row-major (both K-contiguous). Block 128x128, BK=32,
// 128 threads (4 warps 2x2, warp tile 64x64), cp.async double-buffered.
// half_out: C is fp16 [M][N], else fp32.
// ---------------------------------------------------------------------------
#define HBK   32
#define LDAH  40                 // halves per staged row (pad 32->40)
#define ASH   (128 * LDAH)       // halves per A stage
#define LDAH2 (LDAH / 2)         // 20 words

__global__ __launch_bounds__(128, 2)
void hgemm(const __half* __restrict__ A, const __half* __restrict__ Bt,
           const float* __restrict__ bias, void* __restrict__ Cv,
           int M, int N, int K, int half_out)
{
    __shared__ __align__(16) __half As[2][ASH];
    __shared__ __align__(16) __half Bs[2][ASH];

    const int tid  = threadIdx.x;
    const int wid  = tid >> 5;
    const int lane = tid & 31;
    const int g    = lane >> 2;
    const int t    = lane & 3;

    const int bm = blockIdx.y * 128;
    const int bn = blockIdx.x * 128;

    const int warp_m = (wid & 1) * 64;
    const int warp_n = (wid >> 1) * 64;

    const __half* Ab = A  + (size_t)bm * K;
    const __half* Bb = Bt + (size_t)bn * K;

    const uint32_t as_base = (uint32_t)__cvta_generic_to_shared(&As[0][0]);
    const uint32_t bs_base = (uint32_t)__cvta_generic_to_shared(&Bs[0][0]);

    float acc[4][8][4];
#pragma unroll
    for (int mi = 0; mi < 4; mi++)
#pragma unroll
        for (int ni = 0; ni < 8; ni++)
#pragma unroll
            for (int c = 0; c < 4; c++) acc[mi][ni][c] = 0.f;

    // stage: A and B tiles are both 128 rows x 32 halves = 512 16B-chunks each
    auto stage = [&](int s, int k0) {
#pragma unroll
        for (int i = 0; i < 4; i++) {
            int c = i * 128 + tid;
            int r = c >> 2, off = (c & 3) * 8;
            cp16(as_base + (s * ASH + r * LDAH + off) * 2,
                 Ab + (size_t)r * K + k0 + off);
            cp16(bs_base + (s * ASH + r * LDAH + off) * 2,
                 Bb + (size_t)r * K + k0 + off);
        }
        asm volatile("cp.async.commit_group;\n" ::);
    };

    const int nk = K / HBK;
    stage(0, 0);

    for (int kt = 0; kt < nk; kt++) {
        const int s = kt & 1;
        if (kt + 1 < nk) {
            stage(s ^ 1, (kt + 1) * HBK);
            asm volatile("cp.async.wait_group 1;\n" ::);
        } else {
            asm volatile("cp.async.wait_group 0;\n" ::);
        }
        __syncthreads();

        const uint32_t* Aw = (const uint32_t*)&As[s][0];
        const uint32_t* Bw = (const uint32_t*)&Bs[s][0];
#pragma unroll
        for (int kk = 0; kk < 2; kk++) {       // 2 k16-steps per BK32
            uint32_t af[4][4];
#pragma unroll
            for (int mi = 0; mi < 4; mi++) {
                const int mr = warp_m + mi * 16;
                af[mi][0] = Aw[(mr + g)     * LDAH2 + kk * 8 + t];
                af[mi][1] = Aw[(mr + g + 8) * LDAH2 + kk * 8 + t];
                af[mi][2] = Aw[(mr + g)     * LDAH2 + kk * 8 + t + 4];
                af[mi][3] = Aw[(mr + g + 8) * LDAH2 + kk * 8 + t + 4];
            }
#pragma unroll
            for (int ni = 0; ni < 8; ni++) {
                uint32_t bf[2];
                const int nr = warp_n + ni * 8 + g;
                bf[0] = Bw[nr * LDAH2 + kk * 8 + t];
                bf[1] = Bw[nr * LDAH2 + kk * 8 + t + 4];
#pragma unroll
                for (int mi = 0; mi < 4; mi++)
                    mma_f16(acc[mi][ni], af[mi], bf);
            }
        }
        __syncthreads();
    }

    // epilogue: c0=(g,2t) c1=(g,2t+1) c2=(g+8,2t) c3=(g+8,2t+1)
    if (half_out) {
        __half* C = (__half*)Cv;
#pragma unroll
        for (int mi = 0; mi < 4; mi++) {
            const int r0 = bm + warp_m + mi * 16 + g;
            __half* cr0 = C + (size_t)r0 * N + bn;
            __half* cr1 = cr0 + (size_t)8 * N;
#pragma unroll
            for (int ni = 0; ni < 8; ni++) {
                const int cc = warp_n + ni * 8 + 2 * t;
                *(__half2*)(cr0 + cc) = __floats2half2_rn(acc[mi][ni][0], acc[mi][ni][1]);
                *(__half2*)(cr1 + cc) = __floats2half2_rn(acc[mi][ni][2], acc[mi][ni][3]);
            }
        }
    } else {
        float* C = (float*)Cv;
#pragma unroll
        for (int mi = 0; mi < 4; mi++) {
            const int r0 = bm + warp_m + mi * 16 + g;
            float* cr0 = C + (size_t)r0 * N + bn;
            float* cr1 = cr0 + (size_t)8 * N;
#pragma unroll
            for (int ni = 0; ni < 8; ni++) {
                const int cc = warp_n + ni * 8 + 2 * t;
                float bx = 0.f, by = 0.f;
                if (bias) {
                    bx = __ldg(&bias[bn + cc]);
                    by = __ldg(&bias[bn + cc + 1]);
                }
                float2 v0, v1;
                v0.x = acc[mi][ni][0] + bx; v0.y = acc[mi][ni][1] + by;
                v1.x = acc[mi][ni][2] + bx; v1.y = acc[mi][ni][3] + by;
                *(float2*)(cr0 + cc) = v0;
                *(float2*)(cr1 + cc) = v1;
            }
        }
    }
}

// ---------------------------------------------------------------------------
// Flash attention, fp16 m16n8k16 mma, fp16 qkv input, bias via smem,
// softmax exp2 domain. grid = (SEQ/128, B*H); block = 256 (8 warps).
// smem: Ks[64][72]h | Vt[64][72]h | Pw 8x[16][72]h | Bt[63][64]f32 = 53 KB
// ---------------------------------------------------------------------------
#define QTILE 128
#define KTILE 64
#define LDH   72
#define BT_ELEMS (63 * 64)
#define FA_SMEM ((64 * LDH + 64 * LDH + 8 * 16 * LDH) * 2 + BT_ELEMS * 4)

__global__ __launch_bounds__(256)
void flash_attn_f16(const __half* __restrict__ qkv,
                    const float* __restrict__ bias_table,
                    __half* __restrict__ ctx)
{
    extern __shared__ char smraw[];
    __half* Ks = (__half*)smraw;            // [key][dim]
    __half* Vt = Ks + 64 * LDH;             // [dim][key] (transposed)
    __half* Ps = Vt + 64 * LDH;             // 8 warps x [row][key]
    float*  Bt = (float*)(Ps + 8 * 16 * LDH);  // [63][64] bias * log2e

    const int bh = blockIdx.y;
    const int b  = bh / HEADS;
    const int h  = bh % HEADS;
    const int r0 = blockIdx.x * QTILE;

    const int tid  = threadIdx.x;
    const int wid  = tid >> 5;
    const int lane = tid & 31;
    const int g    = lane >> 2;
    const int t    = lane & 3;

    __half* Pw = Ps + wid * 16 * LDH;
    const uint32_t* Kw = (const uint32_t*)Ks;   // half2 view
    const uint32_t* Vw = (const uint32_t*)Vt;
    const uint32_t* Pb = (const uint32_t*)Pw;
    const int LDH2 = LDH / 2;                   // 36 words per row

    // ---- stage per-head bias slice into smem, scaled by log2(e) ----
    for (int v = tid; v < 63 * 63; v += 256) {
        int r = v / 63, c = v - r * 63;
        Bt[r * 64 + c] = __ldg(&bias_table[v * HEADS + h]) * LOG2E;
    }

    // ---- Q A-fragments: load fp16, scale in fp32, repack ----
    const float qscale = 0.125f * LOG2E;
    uint32_t qa[4][4];
    {
        const int qr0 = b * SEQ + r0 + wid * 16;
        const __half* qb = qkv + (size_t)qr0 * QKVCOLS + h * HDIM;
#pragma unroll
        for (int kk = 0; kk < 4; kk++) {
#pragma unroll
            for (int half8 = 0; half8 < 2; half8++) {
                int c = kk * 16 + 2 * t + half8 * 8;
                float2 fx = __half22float2(*(const __half2*)(qb + (size_t)g       * QKVCOLS + c));
                float2 fy = __half22float2(*(const __half2*)(qb + (size_t)(g + 8) * QKVCOLS + c));
                qa[kk][half8 * 2 + 0] = h2u(__floats2half2_rn(fx.x * qscale, fx.y * qscale));
                qa[kk][half8 * 2 + 1] = h2u(__floats2half2_rn(fy.x * qscale, fy.y * qscale));
            }
        }
    }

    float o[8][4];
#pragma unroll
    for (int nt = 0; nt < 8; nt++)
#pragma unroll
        for (int c = 0; c < 4; c++) o[nt][c] = 0.f;

    float m0 = -CUDART_INF_F, m1 = -CUDART_INF_F;
    float l0 = 0.f, l1 = 0.f;

    const int i0 = r0 + wid * 16 + g;
    const int i1 = i0 + 8;
    const int ci0 = (i0 >> 5) * 64 + (i0 & 31) + 2015;
    const int ci1 = (i1 >> 5) * 64 + (i1 & 31) + 2015;

    const int lr = tid >> 2;          // 0..63 loader row (key)
    const int lc = (tid & 3) * 16;    // loader dim base (halves)

    for (int tk = 0; tk < SEQ / KTILE; tk++) {
        __syncthreads();
        // ---- stage K [key][dim] (raw copy) and V transposed [dim][key] ----
        {
            const __half* kb = qkv + (size_t)(b * SEQ + tk * KTILE + lr) * QKVCOLS + DIM + h * HDIM;
            const __half* vb = kb + DIM;
            *(uint4*)&Ks[lr * LDH + lc]     = *(const uint4*)(kb + lc);
            *(uint4*)&Ks[lr * LDH + lc + 8] = *(const uint4*)(kb + lc + 8);
            __half vh[16];
            *(uint4*)&vh[0] = *(const uint4*)(vb + lc);
            *(uint4*)&vh[8] = *(const uint4*)(vb + lc + 8);
#pragma unroll
            for (int d = 0; d < 16; d++)
                Vt[(lc + d) * LDH + lr] = vh[d];
        }
        __syncthreads();

        // ---- S = Q K^T : 4 k16-steps x 8 n-tiles ----
        float s[8][4];
#pragma unroll
        for (int nt = 0; nt < 8; nt++)
#pragma unroll
            for (int c = 0; c < 4; c++) s[nt][c] = 0.f;

#pragma unroll
        for (int kk = 0; kk < 4; kk++) {
#pragma unroll
            for (int nt = 0; nt < 8; nt++) {
                uint32_t bf[2];
                const int key = nt * 8 + g;
                bf[0] = Kw[key * LDH2 + kk * 8 + t];
                bf[1] = Kw[key * LDH2 + kk * 8 + t + 4];
                mma_f16(s[nt], qa[kk], bf);
            }
        }

        // ---- bias (smem) + running softmax (exp2 domain) ----
        float mt0 = -CUDART_INF_F, mt1 = -CUDART_INF_F;
        const int jbase = tk * KTILE + 2 * t;
#pragma unroll
        for (int nt = 0; nt < 8; nt++) {
            int j0 = jbase + nt * 8;
            int cj = j0 + (j0 & ~31);
            s[nt][0] += Bt[ci0 - cj];
            s[nt][1] += Bt[ci0 - cj - 1];
            s[nt][2] += Bt[ci1 - cj];
            s[nt][3] += Bt[ci1 - cj - 1];
            mt0 = fmaxf(mt0, fmaxf(s[nt][0], s[nt][1]));
            mt1 = fmaxf(mt1, fmaxf(s[nt][2], s[nt][3]));
        }
        mt0 = fmaxf(mt0, __shfl_xor_sync(0xffffffffu, mt0, 1));
        mt0 = fmaxf(mt0, __shfl_xor_sync(0xffffffffu, mt0, 2));
        mt1 = fmaxf(mt1, __shfl_xor_sync(0xffffffffu, mt1, 1));
        mt1 = fmaxf(mt1, __shfl_xor_sync(0xffffffffu, mt1, 2));

        float mn0 = fmaxf(m0, mt0);
        float mn1 = fmaxf(m1, mt1);
        float a0 = exp2f(m0 - mn0);
        float a1 = exp2f(m1 - mn1);
        m0 = mn0; m1 = mn1;

        float ls0 = 0.f, ls1 = 0.f;
#pragma unroll
        for (int nt = 0; nt < 8; nt++) {
            float p00 = exp2f(s[nt][0] - mn0);
            float p01 = exp2f(s[nt][1] - mn0);
            float p10 = exp2f(s[nt][2] - mn1);
            float p11 = exp2f(s[nt][3] - mn1);
            ls0 += p00 + p01;
            ls1 += p10 + p11;
            *(__half2*)&Pw[g * LDH + nt * 8 + 2 * t]       = __floats2half2_rn(p00, p01);
            *(__half2*)&Pw[(g + 8) * LDH + nt * 8 + 2 * t] = __floats2half2_rn(p10, p11);
        }
        ls0 += __shfl_xor_sync(0xffffffffu, ls0, 1);
        ls0 += __shfl_xor_sync(0xffffffffu, ls0, 2);
        ls1 += __shfl_xor_sync(0xffffffffu, ls1, 1);
        ls1 += __shfl_xor_sync(0xffffffffu, ls1, 2);
        l0 = l0 * a0 + ls0;
        l1 = l1 * a1 + ls1;

#pragma unroll
        for (int nt = 0; nt < 8; nt++) {
            o[nt][0] *= a0; o[nt][1] *= a0;
            o[nt][2] *= a1; o[nt][3] *= a1;
        }
        __syncwarp();

        // ---- O += P V : 4 k16-steps (keys) x 8 n-tiles (dims) ----
#pragma unroll
        for (int kk = 0; kk < 4; kk++) {
            uint32_t af[4];
            af[0] = Pb[g       * LDH2 + kk * 8 + t];
            af[1] = Pb[(g + 8) * LDH2 + kk * 8 + t];
            af[2] = Pb[g       * LDH2 + kk * 8 + t + 4];
            af[3] = Pb[(g + 8) * LDH2 + kk * 8 + t + 4];
#pragma unroll
            for (int nt = 0; nt < 8; nt++) {
                uint32_t bf[2];
                const int dim = nt * 8 + g;
                bf[0] = Vw[dim * LDH2 + kk * 8 + t];
                bf[1] = Vw[dim * LDH2 + kk * 8 + t + 4];
                mma_f16(o[nt], af, bf);
            }
        }
        __syncwarp();
    }

    // ---- normalize and write ctx (fp16) ----
    float inv0 = 1.f / l0;
    float inv1 = 1.f / l1;
    const int orow0 = b * SEQ + r0 + wid * 16 + g;
    __half* ob0 = ctx + (size_t)orow0 * DIM + h * HDIM + 2 * t;
    __half* ob1 = ctx + (size_t)(orow0 + 8) * DIM + h * HDIM + 2 * t;
#pragma unroll
    for (int nt = 0; nt < 8; nt++) {
        *(__half2*)(ob0 + nt * 8) = __floats2half2_rn(o[nt][0] * inv0, o[nt][1] * inv0);
        *(__half2*)(ob1 + nt * 8) = __floats2half2_rn(o[nt][2] * inv1, o[nt][3] * inv1);
    }
}

// ---------------------------------------------------------------------------
extern "C" void kernel_launch(void* const* d_in, const int* in_sizes, int n_in,
                              void* d_out, int out_size)
{
    const float* x          = (const float*)d_in[0];
    const float* qkv_w      = (const float*)d_in[1];
    const float* proj_w     = (const float*)d_in[2];
    const float* proj_b     = (const float*)d_in[3];
    const float* bias_table = (const float*)d_in[4];
    // d_in[5] = rel_index (int32) — computed analytically, unused
    float* out = (float*)d_out;

    __half *hx, *w1t, *w2t, *qkvh, *ctxh;
    cudaGetSymbolAddress((void**)&hx,   g_hx);
    cudaGetSymbolAddress((void**)&w1t,  g_w1t);
    cudaGetSymbolAddress((void**)&w2t,  g_w2t);
    cudaGetSymbolAddress((void**)&qkvh, g_qkvh);
    cudaGetSymbolAddress((void**)&ctxh, g_ctxh);

    // 0) prep: x -> fp16; weights -> transposed fp16
    cvt_fp16<<<(ROWS * DIM / 4 + 255) / 256, 256>>>(x, hx, ROWS * DIM / 4);
    cvt_t<<<dim3(QKVCOLS / 32, DIM / 32), dim3(32, 8)>>>(qkv_w, w1t, DIM, QKVCOLS);
    cvt_t<<<dim3(DIM / 32, DIM / 32), dim3(32, 8)>>>(proj_w, w2t, DIM, DIM);

    // 1) qkv = x @ qkv_w  (fp16 out)
    {
        dim3 grid(QKVCOLS / 128, ROWS / 128);
        hgemm<<<grid, 128>>>(hx, w1t, nullptr, qkvh, ROWS, QKVCOLS, DIM, 1);
    }

    // 2) flash attention (fp16 in/out)
    {
        cudaFuncSetAttribute(flash_attn_f16, cudaFuncAttributeMaxDynamicSharedMemorySize, FA_SMEM);
        dim3 grid(SEQ / QTILE, BATCH * HEADS);
        flash_attn_f16<<<grid, 256, FA_SMEM>>>(qkvh, bias_table, ctxh);
    }

    // 3) out = ctx @ proj_w + proj_b  (fp32 out)
    {
        dim3 grid(DIM / 128, ROWS / 128);
        hgemm<<<grid, 128>>>(ctxh, w2t, proj_b, out, ROWS, DIM, DIM, 0);
    }
}

// round 12
// speedup vs baseline: 10.9377x; 1.1806x over previous
#include <cuda_runtime.h>
#include <cuda_fp16.h>
#include <cuda_bf16.h>
#include <math_constants.h>
#include <cstdint>
#include <cstring>

// ---------------------------------------------------------------------------
// RelativeAttention: B=8, N=1024, C=768, H=12, hd=64, MAX_DIST=32
// Full fp16 pipeline (fp32 accumulate everywhere):
//   prep:  x -> fp16; qkv_w, proj_w -> transposed fp16 [N][K]
//   qkv  = x @ qkv_w          (fp16 m16n8k16 GEMM, cp.async, fp16 out)
//   attn                      (fp16 mma FA-2: ldmatrix K/V frags, P in regs,
//                              cp.async double-buffered K/V, smem bias)
//   out  = ctx @ proj_w + b   (fp16 m16n8k16 GEMM, fp32 out)
// rel_index analytic: idx = ((i>>5)-(j>>5)+31)*63 + ((i&31)-(j&31)+31)
// ---------------------------------------------------------------------------

#define BATCH   8
#define SEQ     1024
#define DIM     768
#define HEADS   12
#define HDIM    64
#define ROWS    (BATCH * SEQ)       // 8192
#define QKVCOLS (3 * DIM)           // 2304
#define LOG2E   1.4426950408889634f

// scratch (device globals: allocation-free)
__device__ __half g_hx[ROWS * DIM];          // 12.6 MB
__device__ __half g_w1t[QKVCOLS * DIM];      // 3.5 MB  (qkv_w^T)
__device__ __half g_w2t[DIM * DIM];          // 1.2 MB  (proj_w^T)
__device__ __half g_qkvh[ROWS * QKVCOLS];    // 37.7 MB
__device__ __half g_ctxh[ROWS * DIM];        // 12.6 MB

// ---------------------------------------------------------------------------
__device__ __forceinline__ uint32_t h2u(__half2 h) {
    uint32_t u;
    memcpy(&u, &h, 4);
    return u;
}

__device__ __forceinline__ void mma_f16(float c[4], const uint32_t a[4], const uint32_t b[2]) {
    asm volatile(
        "mma.sync.aligned.m16n8k16.row.col.f32.f16.f16.f32 "
        "{%0,%1,%2,%3}, {%4,%5,%6,%7}, {%8,%9}, {%0,%1,%2,%3};\n"
        : "+f"(c[0]), "+f"(c[1]), "+f"(c[2]), "+f"(c[3])
        : "r"(a[0]), "r"(a[1]), "r"(a[2]), "r"(a[3]), "r"(b[0]), "r"(b[1]));
}

__device__ __forceinline__ void cp16(uint32_t smem_addr, const void* gptr) {
    asm volatile("cp.async.ca.shared.global [%0], [%1], 16;\n"
                 :: "r"(smem_addr), "l"(gptr));
}

__device__ __forceinline__ void ldsm_x4(uint32_t r[4], uint32_t addr) {
    asm volatile("ldmatrix.sync.aligned.m8n8.x4.shared.b16 {%0,%1,%2,%3}, [%4];"
                 : "=r"(r[0]), "=r"(r[1]), "=r"(r[2]), "=r"(r[3]) : "r"(addr));
}

__device__ __forceinline__ void ldsm_x4_t(uint32_t r[4], uint32_t addr) {
    asm volatile("ldmatrix.sync.aligned.m8n8.x4.trans.shared.b16 {%0,%1,%2,%3}, [%4];"
                 : "=r"(r[0]), "=r"(r[1]), "=r"(r[2]), "=r"(r[3]) : "r"(addr));
}

// ---------------------------------------------------------------------------
// prep kernels
// ---------------------------------------------------------------------------
__global__ void cvt_fp16(const float* __restrict__ in, __half* __restrict__ out, int n4)
{
    int i = blockIdx.x * blockDim.x + threadIdx.x;
    if (i < n4) {
        float4 v = *(const float4*)(in + i * 4);
        __half2* o = (__half2*)(out + i * 4);
        o[0] = __floats2half2_rn(v.x, v.y);
        o[1] = __floats2half2_rn(v.z, v.w);
    }
}

// in [R][C] fp32 -> out [C][R] fp16; R,C multiples of 32; block (32,8)
__global__ void cvt_t(const float* __restrict__ in, __half* __restrict__ out, int R, int C)
{
    __shared__ __half ts[32][33];
    const int tx = threadIdx.x, ty = threadIdx.y;
    const int c0 = blockIdx.x * 32, r0 = blockIdx.y * 32;
#pragma unroll
    for (int j = 0; j < 4; j++) {
        int r = r0 + ty + j * 8;
        ts[ty + j * 8][tx] = __float2half_rn(in[(size_t)r * C + c0 + tx]);
    }
    __syncthreads();
#pragma unroll
    for (int j = 0; j < 4; j++) {
        out[(size_t)(c0 + ty + j * 8) * R + r0 + tx] = ts[tx][ty + j * 8];
    }
}

// ---------------------------------------------------------------------------
// fp16 GEMM: C[M,N] = A[M,K] @ Bt[N,K]^T (+ bias[N])
// Block 128x128, BK=32, 128 threads (4 warps 2x2, warp tile 64x64),
// cp.async double-buffered. half_out: C fp16, else fp32.
// ---------------------------------------------------------------------------
#define HBK   32
#define LDAH  40
#define ASH   (128 * LDAH)
#define LDAH2 (LDAH / 2)

__global__ __launch_bounds__(128, 2)
void hgemm(const __half* __restrict__ A, const __half* __restrict__ Bt,
           const float* __restrict__ bias, void* __restrict__ Cv,
           int M, int N, int K, int half_out)
{
    __shared__ __align__(16) __half As[2][ASH];
    __shared__ __align__(16) __half Bs[2][ASH];

    const int tid  = threadIdx.x;
    const int wid  = tid >> 5;
    const int lane = tid & 31;
    const int g    = lane >> 2;
    const int t    = lane & 3;

    const int bm = blockIdx.y * 128;
    const int bn = blockIdx.x * 128;

    const int warp_m = (wid & 1) * 64;
    const int warp_n = (wid >> 1) * 64;

    const __half* Ab = A  + (size_t)bm * K;
    const __half* Bb = Bt + (size_t)bn * K;

    const uint32_t as_base = (uint32_t)__cvta_generic_to_shared(&As[0][0]);
    const uint32_t bs_base = (uint32_t)__cvta_generic_to_shared(&Bs[0][0]);

    float acc[4][8][4];
#pragma unroll
    for (int mi = 0; mi < 4; mi++)
#pragma unroll
        for (int ni = 0; ni < 8; ni++)
#pragma unroll
            for (int c = 0; c < 4; c++) acc[mi][ni][c] = 0.f;

    auto stage = [&](int s, int k0) {
#pragma unroll
        for (int i = 0; i < 4; i++) {
            int c = i * 128 + tid;
            int r = c >> 2, off = (c & 3) * 8;
            cp16(as_base + (s * ASH + r * LDAH + off) * 2,
                 Ab + (size_t)r * K + k0 + off);
            cp16(bs_base + (s * ASH + r * LDAH + off) * 2,
                 Bb + (size_t)r * K + k0 + off);
        }
        asm volatile("cp.async.commit_group;\n" ::);
    };

    const int nk = K / HBK;
    stage(0, 0);

    for (int kt = 0; kt < nk; kt++) {
        const int s = kt & 1;
        if (kt + 1 < nk) {
            stage(s ^ 1, (kt + 1) * HBK);
            asm volatile("cp.async.wait_group 1;\n" ::);
        } else {
            asm volatile("cp.async.wait_group 0;\n" ::);
        }
        __syncthreads();

        const uint32_t* Aw = (const uint32_t*)&As[s][0];
        const uint32_t* Bw = (const uint32_t*)&Bs[s][0];
#pragma unroll
        for (int kk = 0; kk < 2; kk++) {
            uint32_t af[4][4];
#pragma unroll
            for (int mi = 0; mi < 4; mi++) {
                const int mr = warp_m + mi * 16;
                af[mi][0] = Aw[(mr + g)     * LDAH2 + kk * 8 + t];
                af[mi][1] = Aw[(mr + g + 8) * LDAH2 + kk * 8 + t];
                af[mi][2] = Aw[(mr + g)     * LDAH2 + kk * 8 + t + 4];
                af[mi][3] = Aw[(mr + g + 8) * LDAH2 + kk * 8 + t + 4];
            }
#pragma unroll
            for (int ni = 0; ni < 8; ni++) {
                uint32_t bf[2];
                const int nr = warp_n + ni * 8 + g;
                bf[0] = Bw[nr * LDAH2 + kk * 8 + t];
                bf[1] = Bw[nr * LDAH2 + kk * 8 + t + 4];
#pragma unroll
                for (int mi = 0; mi < 4; mi++)
                    mma_f16(acc[mi][ni], af[mi], bf);
            }
        }
        __syncthreads();
    }

    if (half_out) {
        __half* C = (__half*)Cv;
#pragma unroll
        for (int mi = 0; mi < 4; mi++) {
            const int r0 = bm + warp_m + mi * 16 + g;
            __half* cr0 = C + (size_t)r0 * N + bn;
            __half* cr1 = cr0 + (size_t)8 * N;
#pragma unroll
            for (int ni = 0; ni < 8; ni++) {
                const int cc = warp_n + ni * 8 + 2 * t;
                *(__half2*)(cr0 + cc) = __floats2half2_rn(acc[mi][ni][0], acc[mi][ni][1]);
                *(__half2*)(cr1 + cc) = __floats2half2_rn(acc[mi][ni][2], acc[mi][ni][3]);
            }
        }
    } else {
        float* C = (float*)Cv;
#pragma unroll
        for (int mi = 0; mi < 4; mi++) {
            const int r0 = bm + warp_m + mi * 16 + g;
            float* cr0 = C + (size_t)r0 * N + bn;
            float* cr1 = cr0 + (size_t)8 * N;
#pragma unroll
            for (int ni = 0; ni < 8; ni++) {
                const int cc = warp_n + ni * 8 + 2 * t;
                float bx = 0.f, by = 0.f;
                if (bias) {
                    bx = __ldg(&bias[bn + cc]);
                    by = __ldg(&bias[bn + cc + 1]);
                }
                float2 v0, v1;
                v0.x = acc[mi][ni][0] + bx; v0.y = acc[mi][ni][1] + by;
                v1.x = acc[mi][ni][2] + bx; v1.y = acc[mi][ni][3] + by;
                *(float2*)(cr0 + cc) = v0;
                *(float2*)(cr1 + cc) = v1;
            }
        }
    }
}

// ---------------------------------------------------------------------------
// Flash attention FA-2 style: fp16 mma, ldmatrix fragments, P in registers,
// cp.async double-buffered K/V, bias via smem, softmax exp2 domain.
// grid = (SEQ/128, B*H); block = 256 (8 warps), 16 query rows per warp.
// smem: Ks[2][64*72]h | Vs[2][64*72]h | Bt[63][64]f = 52.3 KB
// ---------------------------------------------------------------------------
#define QTILE 128
#define KTILE 64
#define LDH   72
#define KVSTG (64 * LDH)
#define BT_ELEMS (63 * 64)
#define FA_SMEM (4 * KVSTG * 2 + BT_ELEMS * 4)

__global__ __launch_bounds__(256)
void flash_attn_f16(const __half* __restrict__ qkv,
                    const float* __restrict__ bias_table,
                    __half* __restrict__ ctx)
{
    extern __shared__ char smraw[];
    __half* Ks = (__half*)smraw;                 // [2][64][LDH]
    __half* Vs = Ks + 2 * KVSTG;                 // [2][64][LDH]
    float*  Bt = (float*)(Vs + 2 * KVSTG);       // [63][64] bias * log2e

    const int bh = blockIdx.y;
    const int b  = bh / HEADS;
    const int h  = bh % HEADS;
    const int r0 = blockIdx.x * QTILE;

    const int tid  = threadIdx.x;
    const int wid  = tid >> 5;
    const int lane = tid & 31;
    const int g    = lane >> 2;
    const int t    = lane & 3;

    const uint32_t ks_base = (uint32_t)__cvta_generic_to_shared(Ks);
    const uint32_t vs_base = (uint32_t)__cvta_generic_to_shared(Vs);

    // ldmatrix per-thread row/col selectors
    const int q8    = lane & 7;
    const int krsel = ((lane >> 4) << 3) + q8;       // K frags
    const int kcsel = ((lane >> 3) & 1) * 8;
    const int vrsel = (((lane >> 3) & 1) << 3) + q8; // V frags (.trans)
    const int vcsel = (lane >> 4) * 8;

    // ---- stage per-head bias slice into smem, scaled by log2(e) ----
    for (int v = tid; v < 63 * 63; v += 256) {
        int r = v / 63, c = v - r * 63;
        Bt[r * 64 + c] = __ldg(&bias_table[v * HEADS + h]) * LOG2E;
    }

    // ---- Q A-fragments: load fp16, scale in fp32, repack ----
    const float qscale = 0.125f * LOG2E;
    uint32_t qa[4][4];
    {
        const int qr0 = b * SEQ + r0 + wid * 16;
        const __half* qb = qkv + (size_t)qr0 * QKVCOLS + h * HDIM;
#pragma unroll
        for (int kk = 0; kk < 4; kk++) {
#pragma unroll
            for (int half8 = 0; half8 < 2; half8++) {
                int c = kk * 16 + 2 * t + half8 * 8;
                float2 fx = __half22float2(*(const __half2*)(qb + (size_t)g       * QKVCOLS + c));
                float2 fy = __half22float2(*(const __half2*)(qb + (size_t)(g + 8) * QKVCOLS + c));
                qa[kk][half8 * 2 + 0] = h2u(__floats2half2_rn(fx.x * qscale, fx.y * qscale));
                qa[kk][half8 * 2 + 1] = h2u(__floats2half2_rn(fy.x * qscale, fy.y * qscale));
            }
        }
    }

    // ---- cp.async K/V staging: 512 chunks each, 2 per thread ----
    const __half* kv0 = qkv + (size_t)(b * SEQ) * QKVCOLS + DIM + h * HDIM;
    auto stage = [&](int s, int tk) {
        const __half* kb = kv0 + (size_t)(tk * KTILE) * QKVCOLS;
#pragma unroll
        for (int i = 0; i < 2; i++) {
            int c   = i * 256 + tid;
            int row = c >> 3, off = (c & 7) * 8;
            const __half* gk = kb + (size_t)row * QKVCOLS + off;
            cp16(ks_base + (s * KVSTG + row * LDH + off) * 2, gk);
            cp16(vs_base + (s * KVSTG + row * LDH + off) * 2, gk + DIM);
        }
        asm volatile("cp.async.commit_group;\n" ::);
    };

    float o[8][4];
#pragma unroll
    for (int nt = 0; nt < 8; nt++)
#pragma unroll
        for (int c = 0; c < 4; c++) o[nt][c] = 0.f;

    float m0 = -CUDART_INF_F, m1 = -CUDART_INF_F;
    float l0 = 0.f, l1 = 0.f;

    const int i0 = r0 + wid * 16 + g;
    const int i1 = i0 + 8;
    const int ci0 = (i0 >> 5) * 64 + (i0 & 31) + 2015;
    const int ci1 = (i1 >> 5) * 64 + (i1 & 31) + 2015;

    const int NT = SEQ / KTILE;   // 16
    stage(0, 0);

    for (int tk = 0; tk < NT; tk++) {
        const int s = tk & 1;
        if (tk + 1 < NT) {
            stage(s ^ 1, tk + 1);
            asm volatile("cp.async.wait_group 1;\n" ::);
        } else {
            asm volatile("cp.async.wait_group 0;\n" ::);
        }
        __syncthreads();

        // ---- S = Q K^T : ldmatrix K frags ----
        float sc[8][4];
#pragma unroll
        for (int nt = 0; nt < 8; nt++)
#pragma unroll
            for (int c = 0; c < 4; c++) sc[nt][c] = 0.f;

#pragma unroll
        for (int kk = 0; kk < 4; kk++) {
#pragma unroll
            for (int ntp = 0; ntp < 4; ntp++) {
                uint32_t kf[4];
                ldsm_x4(kf, ks_base + (s * KVSTG + (ntp * 16 + krsel) * LDH + kk * 16 + kcsel) * 2);
                mma_f16(sc[2 * ntp],     qa[kk], &kf[0]);
                mma_f16(sc[2 * ntp + 1], qa[kk], &kf[2]);
            }
        }

        // ---- bias (smem) + running softmax (exp2 domain), P -> registers ----
        float mt0 = -CUDART_INF_F, mt1 = -CUDART_INF_F;
        const int jbase = tk * KTILE + 2 * t;
#pragma unroll
        for (int nt = 0; nt < 8; nt++) {
            int j0 = jbase + nt * 8;
            int cj = j0 + (j0 & ~31);
            sc[nt][0] += Bt[ci0 - cj];
            sc[nt][1] += Bt[ci0 - cj - 1];
            sc[nt][2] += Bt[ci1 - cj];
            sc[nt][3] += Bt[ci1 - cj - 1];
            mt0 = fmaxf(mt0, fmaxf(sc[nt][0], sc[nt][1]));
            mt1 = fmaxf(mt1, fmaxf(sc[nt][2], sc[nt][3]));
        }
        mt0 = fmaxf(mt0, __shfl_xor_sync(0xffffffffu, mt0, 1));
        mt0 = fmaxf(mt0, __shfl_xor_sync(0xffffffffu, mt0, 2));
        mt1 = fmaxf(mt1, __shfl_xor_sync(0xffffffffu, mt1, 1));
        mt1 = fmaxf(mt1, __shfl_xor_sync(0xffffffffu, mt1, 2));

        float mn0 = fmaxf(m0, mt0);
        float mn1 = fmaxf(m1, mt1);
        float a0 = exp2f(m0 - mn0);
        float a1 = exp2f(m1 - mn1);
        m0 = mn0; m1 = mn1;

        uint32_t pa[4][4];
        float ls0 = 0.f, ls1 = 0.f;
#pragma unroll
        for (int nt = 0; nt < 8; nt++) {
            float p00 = exp2f(sc[nt][0] - mn0);
            float p01 = exp2f(sc[nt][1] - mn0);
            float p10 = exp2f(sc[nt][2] - mn1);
            float p11 = exp2f(sc[nt][3] - mn1);
            ls0 += p00 + p01;
            ls1 += p10 + p11;
            pa[nt >> 1][(nt & 1) * 2 + 0] = h2u(__floats2half2_rn(p00, p01));
            pa[nt >> 1][(nt & 1) * 2 + 1] = h2u(__floats2half2_rn(p10, p11));
        }
        ls0 += __shfl_xor_sync(0xffffffffu, ls0, 1);
        ls0 += __shfl_xor_sync(0xffffffffu, ls0, 2);
        ls1 += __shfl_xor_sync(0xffffffffu, ls1, 1);
        ls1 += __shfl_xor_sync(0xffffffffu, ls1, 2);
        l0 = l0 * a0 + ls0;
        l1 = l1 * a1 + ls1;

#pragma unroll
        for (int nt = 0; nt < 8; nt++) {
            o[nt][0] *= a0; o[nt][1] *= a0;
            o[nt][2] *= a1; o[nt][3] *= a1;
        }

        // ---- O += P V : ldmatrix.trans V frags, P from registers ----
#pragma unroll
        for (int kk = 0; kk < 4; kk++) {
#pragma unroll
            for (int ntp = 0; ntp < 4; ntp++) {
                uint32_t vf[4];
                ldsm_x4_t(vf, vs_base + (s * KVSTG + (kk * 16 + vrsel) * LDH + ntp * 16 + vcsel) * 2);
                mma_f16(o[2 * ntp],     pa[kk], &vf[0]);
                mma_f16(o[2 * ntp + 1], pa[kk], &vf[2]);
            }
        }
        __syncthreads();
    }

    // ---- normalize and write ctx (fp16) ----
    float inv0 = 1.f / l0;
    float inv1 = 1.f / l1;
    const int orow0 = b * SEQ + r0 + wid * 16 + g;
    __half* ob0 = ctx + (size_t)orow0 * DIM + h * HDIM + 2 * t;
    __half* ob1 = ctx + (size_t)(orow0 + 8) * DIM + h * HDIM + 2 * t;
#pragma unroll
    for (int nt = 0; nt < 8; nt++) {
        *(__half2*)(ob0 + nt * 8) = __floats2half2_rn(o[nt][0] * inv0, o[nt][1] * inv0);
        *(__half2*)(ob1 + nt * 8) = __floats2half2_rn(o[nt][2] * inv1, o[nt][3] * inv1);
    }
}

// ---------------------------------------------------------------------------
extern "C" void kernel_launch(void* const* d_in, const int* in_sizes, int n_in,
                              void* d_out, int out_size)
{
    const float* x          = (const float*)d_in[0];
    const float* qkv_w      = (const float*)d_in[1];
    const float* proj_w     = (const float*)d_in[2];
    const float* proj_b     = (const float*)d_in[3];
    const float* bias_table = (const float*)d_in[4];
    // d_in[5] = rel_index (int32) — computed analytically, unused
    float* out = (float*)d_out;

    __half *hx, *w1t, *w2t, *qkvh, *ctxh;
    cudaGetSymbolAddress((void**)&hx,   g_hx);
    cudaGetSymbolAddress((void**)&w1t,  g_w1t);
    cudaGetSymbolAddress((void**)&w2t,  g_w2t);
    cudaGetSymbolAddress((void**)&qkvh, g_qkvh);
    cudaGetSymbolAddress((void**)&ctxh, g_ctxh);

    // 0) prep: x -> fp16; weights -> transposed fp16
    cvt_fp16<<<(ROWS * DIM / 4 + 255) / 256, 256>>>(x, hx, ROWS * DIM / 4);
    cvt_t<<<dim3(QKVCOLS / 32, DIM / 32), dim3(32, 8)>>>(qkv_w, w1t, DIM, QKVCOLS);
    cvt_t<<<dim3(DIM / 32, DIM / 32), dim3(32, 8)>>>(proj_w, w2t, DIM, DIM);

    // 1) qkv = x @ qkv_w  (fp16 out)
    {
        dim3 grid(QKVCOLS / 128, ROWS / 128);
        hgemm<<<grid, 128>>>(hx, w1t, nullptr, qkvh, ROWS, QKVCOLS, DIM, 1);
    }

    // 2) flash attention (fp16 in/out)
    {
        cudaFuncSetAttribute(flash_attn_f16, cudaFuncAttributeMaxDynamicSharedMemorySize, FA_SMEM);
        dim3 grid(SEQ / QTILE, BATCH * HEADS);
        flash_attn_f16<<<grid, 256, FA_SMEM>>>(qkvh, bias_table, ctxh);
    }

    // 3) out = ctx @ proj_w + proj_b  (fp32 out)
    {
        dim3 grid(DIM / 128, ROWS / 128);
        hgemm<<<grid, 128>>>(ctxh, w2t, proj_b, out, ROWS, DIM, DIM, 0);
    }
}

// round 14
// speedup vs baseline: 12.4345x; 1.1368x over previous
#include <cuda_runtime.h>
#include <cuda_fp16.h>
#include <cuda_bf16.h>
#include <math_constants.h>
#include <cstdint>
#include <cstring>

// ---------------------------------------------------------------------------
// RelativeAttention: B=8, N=1024, C=768, H=12, hd=64, MAX_DIST=32
// Full fp16 pipeline (fp32 accumulate everywhere):
//   prep:  x -> fp16; qkv_w, proj_w -> transposed fp16 [N][K]
//   qkv  = x @ qkv_w          (fp16 m16n8k16 GEMM, cp.async, ldmatrix frags)
//   attn                      (fp16 mma FA-2: ldmatrix K/V frags, P in regs)
//   out  = ctx @ proj_w + b   (fp16 m16n8k16 GEMM, fp32 out)
// rel_index analytic: idx = ((i>>5)-(j>>5)+31)*63 + ((i&31)-(j&31)+31)
// ---------------------------------------------------------------------------

#define BATCH   8
#define SEQ     1024
#define DIM     768
#define HEADS   12
#define HDIM    64
#define ROWS    (BATCH * SEQ)       // 8192
#define QKVCOLS (3 * DIM)           // 2304
#define LOG2E   1.4426950408889634f

// scratch (device globals: allocation-free)
__device__ __half g_hx[ROWS * DIM];          // 12.6 MB
__device__ __half g_w1t[QKVCOLS * DIM];      // 3.5 MB  (qkv_w^T)
__device__ __half g_w2t[DIM * DIM];          // 1.2 MB  (proj_w^T)
__device__ __half g_qkvh[ROWS * QKVCOLS];    // 37.7 MB
__device__ __half g_ctxh[ROWS * DIM];        // 12.6 MB

// ---------------------------------------------------------------------------
__device__ __forceinline__ uint32_t h2u(__half2 h) {
    uint32_t u;
    memcpy(&u, &h, 4);
    return u;
}

__device__ __forceinline__ void mma_f16(float c[4], const uint32_t a[4], const uint32_t b[2]) {
    asm volatile(
        "mma.sync.aligned.m16n8k16.row.col.f32.f16.f16.f32 "
        "{%0,%1,%2,%3}, {%4,%5,%6,%7}, {%8,%9}, {%0,%1,%2,%3};\n"
        : "+f"(c[0]), "+f"(c[1]), "+f"(c[2]), "+f"(c[3])
        : "r"(a[0]), "r"(a[1]), "r"(a[2]), "r"(a[3]), "r"(b[0]), "r"(b[1]));
}

__device__ __forceinline__ void cp16(uint32_t smem_addr, const void* gptr) {
    asm volatile("cp.async.ca.shared.global [%0], [%1], 16;\n"
                 :: "r"(smem_addr), "l"(gptr));
}

__device__ __forceinline__ void ldsm_x4(uint32_t r[4], uint32_t addr) {
    asm volatile("ldmatrix.sync.aligned.m8n8.x4.shared.b16 {%0,%1,%2,%3}, [%4];"
                 : "=r"(r[0]), "=r"(r[1]), "=r"(r[2]), "=r"(r[3]) : "r"(addr));
}

__device__ __forceinline__ void ldsm_x4_t(uint32_t r[4], uint32_t addr) {
    asm volatile("ldmatrix.sync.aligned.m8n8.x4.trans.shared.b16 {%0,%1,%2,%3}, [%4];"
                 : "=r"(r[0]), "=r"(r[1]), "=r"(r[2]), "=r"(r[3]) : "r"(addr));
}

// ---------------------------------------------------------------------------
// prep kernels
// ---------------------------------------------------------------------------
__global__ void cvt_fp16(const float* __restrict__ in, __half* __restrict__ out, int n4)
{
    int i = blockIdx.x * blockDim.x + threadIdx.x;
    if (i < n4) {
        float4 v = *(const float4*)(in + i * 4);
        __half2* o = (__half2*)(out + i * 4);
        o[0] = __floats2half2_rn(v.x, v.y);
        o[1] = __floats2half2_rn(v.z, v.w);
    }
}

// in [R][C] fp32 -> out [C][R] fp16; R,C multiples of 32; block (32,8)
__global__ void cvt_t(const float* __restrict__ in, __half* __restrict__ out, int R, int C)
{
    __shared__ __half ts[32][33];
    const int tx = threadIdx.x, ty = threadIdx.y;
    const int c0 = blockIdx.x * 32, r0 = blockIdx.y * 32;
#pragma unroll
    for (int j = 0; j < 4; j++) {
        int r = r0 + ty + j * 8;
        ts[ty + j * 8][tx] = __float2half_rn(in[(size_t)r * C + c0 + tx]);
    }
    __syncthreads();
#pragma unroll
    for (int j = 0; j < 4; j++) {
        out[(size_t)(c0 + ty + j * 8) * R + r0 + tx] = ts[tx][ty + j * 8];
    }
}

// ---------------------------------------------------------------------------
// fp16 GEMM: C[M,N] = A[M,K] @ Bt[N,K]^T (+ bias[N])
// Block 128x128, BK=32, 128 threads (4 warps 2x2, warp tile 64x64),
// cp.async double-buffered, ldmatrix fragment loads.
// half_out: C fp16, else fp32.
// ---------------------------------------------------------------------------
#define HBK   32
#define LDAH  40
#define ASH   (128 * LDAH)

__global__ __launch_bounds__(128, 2)
void hgemm(const __half* __restrict__ A, const __half* __restrict__ Bt,
           const float* __restrict__ bias, void* __restrict__ Cv,
           int M, int N, int K, int half_out)
{
    __shared__ __align__(16) __half As[2][ASH];
    __shared__ __align__(16) __half Bs[2][ASH];

    const int tid  = threadIdx.x;
    const int wid  = tid >> 5;
    const int lane = tid & 31;
    const int g    = lane >> 2;
    const int t    = lane & 3;

    const int bm = blockIdx.y * 128;
    const int bn = blockIdx.x * 128;

    const int warp_m = (wid & 1) * 64;
    const int warp_n = (wid >> 1) * 64;

    // ldmatrix selectors
    const int arsel = lane & 15;                       // A: row in m16
    const int acsel = (lane >> 4) * 8;                 // A: col base
    const int brsel = ((lane >> 4) << 3) + (lane & 7); // B: row in n16
    const int bcsel = ((lane >> 3) & 1) * 8;           // B: col base

    const __half* Ab = A  + (size_t)bm * K;
    const __half* Bb = Bt + (size_t)bn * K;

    const uint32_t as_base = (uint32_t)__cvta_generic_to_shared(&As[0][0]);
    const uint32_t bs_base = (uint32_t)__cvta_generic_to_shared(&Bs[0][0]);

    float acc[4][8][4];
#pragma unroll
    for (int mi = 0; mi < 4; mi++)
#pragma unroll
        for (int ni = 0; ni < 8; ni++)
#pragma unroll
            for (int c = 0; c < 4; c++) acc[mi][ni][c] = 0.f;

    auto stage = [&](int s, int k0) {
#pragma unroll
        for (int i = 0; i < 4; i++) {
            int c = i * 128 + tid;
            int r = c >> 2, off = (c & 3) * 8;
            cp16(as_base + (s * ASH + r * LDAH + off) * 2,
                 Ab + (size_t)r * K + k0 + off);
            cp16(bs_base + (s * ASH + r * LDAH + off) * 2,
                 Bb + (size_t)r * K + k0 + off);
        }
        asm volatile("cp.async.commit_group;\n" ::);
    };

    const int nk = K / HBK;
    stage(0, 0);

    for (int kt = 0; kt < nk; kt++) {
        const int s = kt & 1;
        if (kt + 1 < nk) {
            stage(s ^ 1, (kt + 1) * HBK);
            asm volatile("cp.async.wait_group 1;\n" ::);
        } else {
            asm volatile("cp.async.wait_group 0;\n" ::);
        }
        __syncthreads();

        const uint32_t a_tile = as_base + s * ASH * 2;
        const uint32_t b_tile = bs_base + s * ASH * 2;
#pragma unroll
        for (int kk = 0; kk < 2; kk++) {
            uint32_t af[4][4];
#pragma unroll
            for (int mi = 0; mi < 4; mi++)
                ldsm_x4(af[mi], a_tile + ((warp_m + mi * 16 + arsel) * LDAH + kk * 16 + acsel) * 2);
#pragma unroll
            for (int np = 0; np < 4; np++) {
                uint32_t bf[4];
                ldsm_x4(bf, b_tile + ((warp_n + np * 16 + brsel) * LDAH + kk * 16 + bcsel) * 2);
#pragma unroll
                for (int mi = 0; mi < 4; mi++) {
                    mma_f16(acc[mi][2 * np],     af[mi], &bf[0]);
                    mma_f16(acc[mi][2 * np + 1], af[mi], &bf[2]);
                }
            }
        }
        __syncthreads();
    }

    if (half_out) {
        __half* C = (__half*)Cv;
#pragma unroll
        for (int mi = 0; mi < 4; mi++) {
            const int r0 = bm + warp_m + mi * 16 + g;
            __half* cr0 = C + (size_t)r0 * N + bn;
            __half* cr1 = cr0 + (size_t)8 * N;
#pragma unroll
            for (int ni = 0; ni < 8; ni++) {
                const int cc = warp_n + ni * 8 + 2 * t;
                *(__half2*)(cr0 + cc) = __floats2half2_rn(acc[mi][ni][0], acc[mi][ni][1]);
                *(__half2*)(cr1 + cc) = __floats2half2_rn(acc[mi][ni][2], acc[mi][ni][3]);
            }
        }
    } else {
        float* C = (float*)Cv;
#pragma unroll
        for (int mi = 0; mi < 4; mi++) {
            const int r0 = bm + warp_m + mi * 16 + g;
            float* cr0 = C + (size_t)r0 * N + bn;
            float* cr1 = cr0 + (size_t)8 * N;
#pragma unroll
            for (int ni = 0; ni < 8; ni++) {
                const int cc = warp_n + ni * 8 + 2 * t;
                float bx = 0.f, by = 0.f;
                if (bias) {
                    bx = __ldg(&bias[bn + cc]);
                    by = __ldg(&bias[bn + cc + 1]);
                }
                float2 v0, v1;
                v0.x = acc[mi][ni][0] + bx; v0.y = acc[mi][ni][1] + by;
                v1.x = acc[mi][ni][2] + bx; v1.y = acc[mi][ni][3] + by;
                *(float2*)(cr0 + cc) = v0;
                *(float2*)(cr1 + cc) = v1;
            }
        }
    }
}

// ---------------------------------------------------------------------------
// Flash attention FA-2 style: fp16 mma, ldmatrix fragments, P in registers,
// cp.async double-buffered K/V, bias via smem, softmax exp2 domain.
// grid = (SEQ/128, B*H); block = 256 (8 warps), 16 query rows per warp.
// smem: Ks[2][64*72]h | Vs[2][64*72]h | Bt[63][64]f = 52.3 KB
// ---------------------------------------------------------------------------
#define QTILE 128
#define KTILE 64
#define LDH   72
#define KVSTG (64 * LDH)
#define BT_ELEMS (63 * 64)
#define FA_SMEM (4 * KVSTG * 2 + BT_ELEMS * 4)

__global__ __launch_bounds__(256)
void flash_attn_f16(const __half* __restrict__ qkv,
                    const float* __restrict__ bias_table,
                    __half* __restrict__ ctx)
{
    extern __shared__ char smraw[];
    __half* Ks = (__half*)smraw;                 // [2][64][LDH]
    __half* Vs = Ks + 2 * KVSTG;                 // [2][64][LDH]
    float*  Bt = (float*)(Vs + 2 * KVSTG);       // [63][64] bias * log2e

    const int bh = blockIdx.y;
    const int b  = bh / HEADS;
    const int h  = bh % HEADS;
    const int r0 = blockIdx.x * QTILE;

    const int tid  = threadIdx.x;
    const int wid  = tid >> 5;
    const int lane = tid & 31;
    const int g    = lane >> 2;
    const int t    = lane & 3;

    const uint32_t ks_base = (uint32_t)__cvta_generic_to_shared(Ks);
    const uint32_t vs_base = (uint32_t)__cvta_generic_to_shared(Vs);

    const int q8    = lane & 7;
    const int krsel = ((lane >> 4) << 3) + q8;       // K frags
    const int kcsel = ((lane >> 3) & 1) * 8;
    const int vrsel = (((lane >> 3) & 1) << 3) + q8; // V frags (.trans)
    const int vcsel = (lane >> 4) * 8;

    // ---- stage per-head bias slice into smem, scaled by log2(e) ----
    for (int v = tid; v < 63 * 63; v += 256) {
        int r = v / 63, c = v - r * 63;
        Bt[r * 64 + c] = __ldg(&bias_table[v * HEADS + h]) * LOG2E;
    }

    // ---- Q A-fragments: load fp16, scale in fp32, repack ----
    const float qscale = 0.125f * LOG2E;
    uint32_t qa[4][4];
    {
        const int qr0 = b * SEQ + r0 + wid * 16;
        const __half* qb = qkv + (size_t)qr0 * QKVCOLS + h * HDIM;
#pragma unroll
        for (int kk = 0; kk < 4; kk++) {
#pragma unroll
            for (int half8 = 0; half8 < 2; half8++) {
                int c = kk * 16 + 2 * t + half8 * 8;
                float2 fx = __half22float2(*(const __half2*)(qb + (size_t)g       * QKVCOLS + c));
                float2 fy = __half22float2(*(const __half2*)(qb + (size_t)(g + 8) * QKVCOLS + c));
                qa[kk][half8 * 2 + 0] = h2u(__floats2half2_rn(fx.x * qscale, fx.y * qscale));
                qa[kk][half8 * 2 + 1] = h2u(__floats2half2_rn(fy.x * qscale, fy.y * qscale));
            }
        }
    }

    // ---- cp.async K/V staging: 512 chunks each, 2 per thread ----
    const __half* kv0 = qkv + (size_t)(b * SEQ) * QKVCOLS + DIM + h * HDIM;
    auto stage = [&](int s, int tk) {
        const __half* kb = kv0 + (size_t)(tk * KTILE) * QKVCOLS;
#pragma unroll
        for (int i = 0; i < 2; i++) {
            int c   = i * 256 + tid;
            int row = c >> 3, off = (c & 7) * 8;
            const __half* gk = kb + (size_t)row * QKVCOLS + off;
            cp16(ks_base + (s * KVSTG + row * LDH + off) * 2, gk);
            cp16(vs_base + (s * KVSTG + row * LDH + off) * 2, gk + DIM);
        }
        asm volatile("cp.async.commit_group;\n" ::);
    };

    float o[8][4];
#pragma unroll
    for (int nt = 0; nt < 8; nt++)
#pragma unroll
        for (int c = 0; c < 4; c++) o[nt][c] = 0.f;

    float m0 = -CUDART_INF_F, m1 = -CUDART_INF_F;
    float l0 = 0.f, l1 = 0.f;

    const int i0 = r0 + wid * 16 + g;
    const int i1 = i0 + 8;
    const int ci0 = (i0 >> 5) * 64 + (i0 & 31) + 2015;
    const int ci1 = (i1 >> 5) * 64 + (i1 & 31) + 2015;

    const int NT = SEQ / KTILE;   // 16
    stage(0, 0);

    for (int tk = 0; tk < NT; tk++) {
        const int s = tk & 1;
        if (tk + 1 < NT) {
            stage(s ^ 1, tk + 1);
            asm volatile("cp.async.wait_group 1;\n" ::);
        } else {
            asm volatile("cp.async.wait_group 0;\n" ::);
        }
        __syncthreads();

        // ---- S = Q K^T : ldmatrix K frags ----
        float sc[8][4];
#pragma unroll
        for (int nt = 0; nt < 8; nt++)
#pragma unroll
            for (int c = 0; c < 4; c++) sc[nt][c] = 0.f;

#pragma unroll
        for (int kk = 0; kk < 4; kk++) {
#pragma unroll
            for (int ntp = 0; ntp < 4; ntp++) {
                uint32_t kf[4];
                ldsm_x4(kf, ks_base + (s * KVSTG + (ntp * 16 + krsel) * LDH + kk * 16 + kcsel) * 2);
                mma_f16(sc[2 * ntp],     qa[kk], &kf[0]);
                mma_f16(sc[2 * ntp + 1], qa[kk], &kf[2]);
            }
        }

        // ---- bias (smem) + running softmax (exp2 domain), P -> registers ----
        float mt0 = -CUDART_INF_F, mt1 = -CUDART_INF_F;
        const int jbase = tk * KTILE + 2 * t;
#pragma unroll
        for (int nt = 0; nt < 8; nt++) {
            int j0 = jbase + nt * 8;
            int cj = j0 + (j0 & ~31);
            sc[nt][0] += Bt[ci0 - cj];
            sc[nt][1] += Bt[ci0 - cj - 1];
            sc[nt][2] += Bt[ci1 - cj];
            sc[nt][3] += Bt[ci1 - cj - 1];
            mt0 = fmaxf(mt0, fmaxf(sc[nt][0], sc[nt][1]));
            mt1 = fmaxf(mt1, fmaxf(sc[nt][2], sc[nt][3]));
        }
        mt0 = fmaxf(mt0, __shfl_xor_sync(0xffffffffu, mt0, 1));
        mt0 = fmaxf(mt0, __shfl_xor_sync(0xffffffffu, mt0, 2));
        mt1 = fmaxf(mt1, __shfl_xor_sync(0xffffffffu, mt1, 1));
        mt1 = fmaxf(mt1, __shfl_xor_sync(0xffffffffu, mt1, 2));

        float mn0 = fmaxf(m0, mt0);
        float mn1 = fmaxf(m1, mt1);
        float a0 = exp2f(m0 - mn0);
        float a1 = exp2f(m1 - mn1);
        m0 = mn0; m1 = mn1;

        uint32_t pa[4][4];
        float ls0 = 0.f, ls1 = 0.f;
#pragma unroll
        for (int nt = 0; nt < 8; nt++) {
            float p00 = exp2f(sc[nt][0] - mn0);
            float p01 = exp2f(sc[nt][1] - mn0);
            float p10 = exp2f(sc[nt][2] - mn1);
            float p11 = exp2f(sc[nt][3] - mn1);
            ls0 += p00 + p01;
            ls1 += p10 + p11;
            pa[nt >> 1][(nt & 1) * 2 + 0] = h2u(__floats2half2_rn(p00, p01));
            pa[nt >> 1][(nt & 1) * 2 + 1] = h2u(__floats2half2_rn(p10, p11));
        }
        ls0 += __shfl_xor_sync(0xffffffffu, ls0, 1);
        ls0 += __shfl_xor_sync(0xffffffffu, ls0, 2);
        ls1 += __shfl_xor_sync(0xffffffffu, ls1, 1);
        ls1 += __shfl_xor_sync(0xffffffffu, ls1, 2);
        l0 = l0 * a0 + ls0;
        l1 = l1 * a1 + ls1;

#pragma unroll
        for (int nt = 0; nt < 8; nt++) {
            o[nt][0] *= a0; o[nt][1] *= a0;
            o[nt][2] *= a1; o[nt][3] *= a1;
        }

        // ---- O += P V : ldmatrix.trans V frags, P from registers ----
#pragma unroll
        for (int kk = 0; kk < 4; kk++) {
#pragma unroll
            for (int ntp = 0; ntp < 4; ntp++) {
                uint32_t vf[4];
                ldsm_x4_t(vf, vs_base + (s * KVSTG + (kk * 16 + vrsel) * LDH + ntp * 16 + vcsel) * 2);
                mma_f16(o[2 * ntp],     pa[kk], &vf[0]);
                mma_f16(o[2 * ntp + 1], pa[kk], &vf[2]);
            }
        }
        __syncthreads();
    }

    // ---- normalize and write ctx (fp16) ----
    float inv0 = 1.f / l0;
    float inv1 = 1.f / l1;
    const int orow0 = b * SEQ + r0 + wid * 16 + g;
    __half* ob0 = ctx + (size_t)orow0 * DIM + h * HDIM + 2 * t;
    __half* ob1 = ctx + (size_t)(orow0 + 8) * DIM + h * HDIM + 2 * t;
#pragma unroll
    for (int nt = 0; nt < 8; nt++) {
        *(__half2*)(ob0 + nt * 8) = __floats2half2_rn(o[nt][0] * inv0, o[nt][1] * inv0);
        *(__half2*)(ob1 + nt * 8) = __floats2half2_rn(o[nt][2] * inv1, o[nt][3] * inv1);
    }
}

// ---------------------------------------------------------------------------
extern "C" void kernel_launch(void* const* d_in, const int* in_sizes, int n_in,
                              void* d_out, int out_size)
{
    const float* x          = (const float*)d_in[0];
    const float* qkv_w      = (const float*)d_in[1];
    const float* proj_w     = (const float*)d_in[2];
    const float* proj_b     = (const float*)d_in[3];
    const float* bias_table = (const float*)d_in[4];
    // d_in[5] = rel_index (int32) — computed analytically, unused
    float* out = (float*)d_out;

    __half *hx, *w1t, *w2t, *qkvh, *ctxh;
    cudaGetSymbolAddress((void**)&hx,   g_hx);
    cudaGetSymbolAddress((void**)&w1t,  g_w1t);
    cudaGetSymbolAddress((void**)&w2t,  g_w2t);
    cudaGetSymbolAddress((void**)&qkvh, g_qkvh);
    cudaGetSymbolAddress((void**)&ctxh, g_ctxh);

    // 0) prep: x -> fp16; weights -> transposed fp16
    cvt_fp16<<<(ROWS * DIM / 4 + 255) / 256, 256>>>(x, hx, ROWS * DIM / 4);
    cvt_t<<<dim3(QKVCOLS / 32, DIM / 32), dim3(32, 8)>>>(qkv_w, w1t, DIM, QKVCOLS);
    cvt_t<<<dim3(DIM / 32, DIM / 32), dim3(32, 8)>>>(proj_w, w2t, DIM, DIM);

    // 1) qkv = x @ qkv_w  (fp16 out)
    {
        dim3 grid(QKVCOLS / 128, ROWS / 128);
        hgemm<<<grid, 128>>>(hx, w1t, nullptr, qkvh, ROWS, QKVCOLS, DIM, 1);
    }

    // 2) flash attention (fp16 in/out)
    {
        cudaFuncSetAttribute(flash_attn_f16, cudaFuncAttributeMaxDynamicSharedMemorySize, FA_SMEM);
        dim3 grid(SEQ / QTILE, BATCH * HEADS);
        flash_attn_f16<<<grid, 256, FA_SMEM>>>(qkvh, bias_table, ctxh);
    }

    // 3) out = ctx @ proj_w + proj_b  (fp32 out)
    {
        dim3 grid(DIM / 128, ROWS / 128);
        hgemm<<<grid, 128>>>(ctxh, w2t, proj_b, out, ROWS, DIM, DIM, 0);
    }
}